// round 12
// baseline (speedup 1.0000x reference)
#include <cuda_runtime.h>
#include <cuda_bf16.h>
#include <math.h>
#include <stdint.h>

// ---------------- problem dims (fixed) ----------------
#define SQ   1024
#define DM   1024
#define NH   16
#define NG   4
#define HDIM 64
#define HPG  4
#define GHD  256
#define NL   4
#define DFF  4096
#define NV   32000
#define QKV  1536      // DM + 2*GHD
#define RTD  8.0f
#define RTDM 32.0f

// ---------------- device scratch ----------------
__device__ float g_h   [SQ * DM];
__device__ float g_qkv [SQ * QKV];
__device__ float g_t   [SQ * DM];
__device__ float g_qkvb[NL * QKV];
__device__ float g_biog[NL * 2 * DFF];
__device__ float g_siog[NL * 2 * DFF];

__device__ __align__(16) __nv_bfloat16 g_hb   [SQ * DM];
__device__ __align__(16) __nv_bfloat16 g_attnb[SQ * DM];
__device__ __align__(16) __nv_bfloat16 g_ub   [SQ * DFF];
__device__ __align__(16) __nv_bfloat16 g_qkvw [(long)NL * QKV * DM];
__device__ __align__(16) __nv_bfloat16 g_wiog [(long)NL * 2 * DFF * DM];
__device__ __align__(16) __nv_bfloat16 g_wout [(long)NL * DM * DFF];
__device__ __align__(16) __nv_bfloat16 g_ow   [(long)NL * DM * DM];
__device__ __align__(16) __nv_bfloat16 g_outw [(long)NV * DM];

__device__ __forceinline__ uint32_t packbf(float x, float y) {
    __nv_bfloat162 t = __floats2bfloat162_rn(x, y);
    return *reinterpret_cast<uint32_t*>(&t);
}
__device__ __forceinline__ uint32_t packbf_res(float x, float y, uint32_t hi) {
    __nv_bfloat162 h = *reinterpret_cast<__nv_bfloat162*>(&hi);
    return packbf(x - __bfloat162float(h.x), y - __bfloat162float(h.y));
}

__device__ __forceinline__ void mma_bf16(float c[4], uint32_t a0, uint32_t a1,
                                         uint32_t a2, uint32_t a3,
                                         uint32_t b0, uint32_t b1) {
    asm volatile(
        "mma.sync.aligned.m16n8k16.row.col.f32.bf16.bf16.f32 "
        "{%0,%1,%2,%3}, {%4,%5,%6,%7}, {%8,%9}, {%0,%1,%2,%3};"
        : "+f"(c[0]), "+f"(c[1]), "+f"(c[2]), "+f"(c[3])
        : "r"(a0), "r"(a1), "r"(a2), "r"(a3), "r"(b0), "r"(b1));
}

__device__ __forceinline__ void ldsm4(uint32_t r[4], uint32_t addr) {
    asm volatile(
        "ldmatrix.sync.aligned.m8n8.x4.shared.b16 {%0,%1,%2,%3}, [%4];"
        : "=r"(r[0]), "=r"(r[1]), "=r"(r[2]), "=r"(r[3]) : "r"(addr));
}

// ================= mega weight-conversion kernel (single launch, MLP=12) =================
#define E_QKVW  1572864L
#define E_WIOG  8388608L
#define E_WOUT  4194304L
#define E_OW    1048576L
#define E_OUTW  8192000L
#define CB0 (E_QKVW)
#define CB1 (CB0 + E_WIOG)
#define CB2 (CB1 + E_WOUT)
#define CB3 (CB2 + E_OW)
#define CB4 (CB3 + E_OUTW)
#define CB5 (CB4 + 1536L)
#define CB6 (CB5 + 16384L)
#define CVT_GRID 8192
#define CVT_STRIDE ((long)CVT_GRID * 256)

__global__ void cvt_all_k(const float* __restrict__ qw, const float* __restrict__ kw,
                          const float* __restrict__ vw, const float* __restrict__ w_in,
                          const float* __restrict__ w_gate, const float* __restrict__ w_out,
                          const float* __restrict__ ow, const float* __restrict__ out_w,
                          const float* __restrict__ qb, const float* __restrict__ kb,
                          const float* __restrict__ vb, const float* __restrict__ b_in,
                          const float* __restrict__ b_gate, const float* __restrict__ s_u,
                          const float* __restrict__ s_v)
{
    const long base = (long)blockIdx.x * 256 + threadIdx.x;
#pragma unroll
    for (int it = 0; it < 12; it++) {
        const long e = base + (long)it * CVT_STRIDE;
        if (e >= CB6) break;
        if (e < CB0) {
            long t = e;
            int l = (int)(t / 393216L);
            int rem = (int)(t - (long)l * 393216L);
            int row = rem >> 8, c4 = rem & 255;
            const float* src;
            if (row < DM)            src = qw + ((long)l * DM  + row)            * DM + c4 * 4;
            else if (row < DM + GHD) src = kw + ((long)l * GHD + row - DM)       * DM + c4 * 4;
            else                     src = vw + ((long)l * GHD + row - DM - GHD) * DM + c4 * 4;
            float4 v = *(const float4*)src;
            ((uint2*)g_qkvw)[t] = make_uint2(packbf(v.x, v.y), packbf(v.z, v.w));
        } else if (e < CB1) {
            long t = e - CB0;
            int l = (int)(t >> 21);
            int rem = (int)(t & 2097151L);
            int r = rem >> 8, c4 = rem & 255;
            const float* src = ((r & 1) ? w_gate : w_in)
                             + ((long)l * DFF + (r >> 1)) * DM + c4 * 4;
            float4 v = *(const float4*)src;
            ((uint2*)g_wiog)[t] = make_uint2(packbf(v.x, v.y), packbf(v.z, v.w));
        } else if (e < CB2) {
            long t = e - CB1;
            float4 v = ((const float4*)w_out)[t];
            ((uint2*)g_wout)[t] = make_uint2(packbf(v.x, v.y), packbf(v.z, v.w));
        } else if (e < CB3) {
            long t = e - CB2;
            float4 v = ((const float4*)ow)[t];
            ((uint2*)g_ow)[t] = make_uint2(packbf(v.x, v.y), packbf(v.z, v.w));
        } else if (e < CB4) {
            long t = e - CB3;
            float4 v = ((const float4*)out_w)[t];
            ((uint2*)g_outw)[t] = make_uint2(packbf(v.x, v.y), packbf(v.z, v.w));
        } else if (e < CB5) {
            int t = (int)(e - CB4);
            int l = t / 384, f4 = (t % 384) * 4;
            float4 v;
            if (f4 < DM)            v = *(const float4*)(qb + (long)l * DM  + f4);
            else if (f4 < DM + GHD) v = *(const float4*)(kb + (long)l * GHD + f4 - DM);
            else                    v = *(const float4*)(vb + (long)l * GHD + f4 - DM - GHD);
            *(float4*)(g_qkvb + (long)l * QKV + f4) = v;
        } else {
            int t = (int)(e - CB5);
            int l = t >> 12, f = t & (DFF - 1);
            g_biog[(long)l * 2 * DFF + 2 * f]     = b_in  [(long)l * DFF + f];
            g_biog[(long)l * 2 * DFF + 2 * f + 1] = b_gate[(long)l * DFF + f];
            g_siog[(long)l * 2 * DFF + 2 * f]     = s_u   [(long)l * DFF + f];
            g_siog[(long)l * 2 * DFF + 2 * f + 1] = s_v   [(long)l * DFF + f] * RTDM;
        }
    }
}

// ================= pure-bf16 TB GEMM, ldmatrix, single-sync mainloop =================
#define TASTR 20

template<int BMT, int BN, int EPI>
__global__ void __launch_bounds__(256, 2)
bf16_gemm_k(const __nv_bfloat16* __restrict__ A, const __nv_bfloat16* __restrict__ B,
            void* __restrict__ Cv, int K, int lda, int ldb, int ldc,
            float alpha, const float* __restrict__ bias,
            const float* __restrict__ scalev, float beta)
{
    constexpr int NF  = (BMT == 128) ? (BN / 16) : (BN / 32);
    constexpr int TAW = BMT * TASTR;
    constexpr int TBW = BN * TASTR;
    __shared__ __align__(16) uint32_t As[2 * TAW];
    __shared__ __align__(16) uint32_t Bs[2 * TBW];

    const int bm = blockIdx.y * BMT;
    const int bn = blockIdx.x * BN;
    const int tid  = threadIdx.x;
    const int wid  = tid >> 5;
    const int lane = tid & 31;
    const int g4   = lane >> 2;
    const int t4   = lane & 3;
    const int wm   = (BMT == 128) ? (wid & 3) * 32 : (wid & 1) * 32;
    const int wn   = (BMT == 128) ? (wid >> 2) * 64 : (wid >> 1) * (BN / 4);

    const uint32_t asb = (uint32_t)__cvta_generic_to_shared(As);
    const uint32_t bsb = (uint32_t)__cvta_generic_to_shared(Bs);
    const uint32_t aFrag = asb + 4u * ((wm + (lane & 15)) * TASTR + (lane >> 4) * 4);
    const uint32_t bFrag = bsb + 4u * ((wn + (lane & 15)) * TASTR + (lane >> 4) * 4);

    const int ra_ = (BMT == 128) ? (tid >> 1) : (tid >> 2);
    const int qa_ = (BMT == 128) ? (tid & 1)  : (tid & 3);
    const int rb_ = (BN  == 128) ? (tid >> 1) : (tid >> 2);
    const int hb_ = (BN  == 128) ? (tid & 1)  : (tid & 3);

    uint4 ra[2], rb[2];

    auto ldg = [&](int k0) {
        if (BMT == 128) {
            const __nv_bfloat16* pa = A + (long)(bm + ra_) * lda + k0 + qa_ * 16;
            ra[0] = *(const uint4*)pa; ra[1] = *(const uint4*)(pa + 8);
        } else {
            const __nv_bfloat16* pa = A + (long)(bm + ra_) * lda + k0 + qa_ * 8;
            ra[0] = *(const uint4*)pa;
        }
        if (BN == 128) {
            const __nv_bfloat16* pb = B + (long)(bn + rb_) * ldb + k0 + hb_ * 16;
            rb[0] = *(const uint4*)pb; rb[1] = *(const uint4*)(pb + 8);
        } else {
            const __nv_bfloat16* pb = B + (long)(bn + rb_) * ldb + k0 + hb_ * 8;
            rb[0] = *(const uint4*)pb;
        }
    };
    auto sts = [&](int buf) {
        if (BMT == 128) {
            uint32_t* da = As + buf * TAW + ra_ * TASTR + qa_ * 8;
            *(uint4*)da = ra[0]; *(uint4*)(da + 4) = ra[1];
        } else {
            uint32_t* da = As + buf * TAW + ra_ * TASTR + qa_ * 4;
            *(uint4*)da = ra[0];
        }
        if (BN == 128) {
            uint32_t* db = Bs + buf * TBW + rb_ * TASTR + hb_ * 8;
            *(uint4*)db = rb[0]; *(uint4*)(db + 4) = rb[1];
        } else {
            uint32_t* db = Bs + buf * TBW + rb_ * TASTR + hb_ * 4;
            *(uint4*)db = rb[0];
        }
    };

    float acc[2][NF][4];
#pragma unroll
    for (int i = 0; i < 2; i++)
#pragma unroll
        for (int j = 0; j < NF; j++)
#pragma unroll
            for (int l = 0; l < 4; l++) acc[i][j][l] = 0.0f;

    ldg(0);
    sts(0);
    __syncthreads();

    const int nsteps = K / 32;
    for (int ks = 0; ks < nsteps; ks++) {
        const bool more = (ks + 1 < nsteps);
        if (more) ldg((ks + 1) * 32);

        const uint32_t aB = aFrag + (ks & 1) * TAW * 4;
        const uint32_t bB = bFrag + (ks & 1) * TBW * 4;

#pragma unroll
        for (int kh = 0; kh < 2; kh++) {
            uint32_t af[2][4];
            ldsm4(af[0], aB + 4u * (kh * 8));
            ldsm4(af[1], aB + 4u * (16 * TASTR + kh * 8));
#pragma unroll
            for (int bf = 0; bf < NF / 2; bf++) {
                uint32_t bb[4];
                ldsm4(bb, bB + 4u * (bf * 16 * TASTR + kh * 8));
                mma_bf16(acc[0][2*bf  ], af[0][0], af[0][1], af[0][2], af[0][3], bb[0], bb[2]);
                mma_bf16(acc[1][2*bf  ], af[1][0], af[1][1], af[1][2], af[1][3], bb[0], bb[2]);
                mma_bf16(acc[0][2*bf+1], af[0][0], af[0][1], af[0][2], af[0][3], bb[1], bb[3]);
                mma_bf16(acc[1][2*bf+1], af[1][0], af[1][1], af[1][2], af[1][3], bb[1], bb[3]);
            }
        }

        if (more) sts((ks + 1) & 1);
        __syncthreads();
    }

#pragma unroll
    for (int mf = 0; mf < 2; mf++) {
#pragma unroll
        for (int nf = 0; nf < NF; nf++) {
            const int row = bm + wm + mf * 16 + g4;
            const int col = bn + wn + nf * 8 + t4 * 2;
            if (EPI == 0) {
                float* C = (float*)Cv;
                float v0 = acc[mf][nf][0] * alpha;
                float v1 = acc[mf][nf][1] * alpha;
                float v2 = acc[mf][nf][2] * alpha;
                float v3 = acc[mf][nf][3] * alpha;
                if (bias) {
                    float b0 = bias[col], b1 = bias[col + 1];
                    v0 += b0; v1 += b1; v2 += b0; v3 += b1;
                }
                if (scalev) {
                    float s0 = scalev[col] * beta, s1 = scalev[col + 1] * beta;
                    v0 *= s0; v1 *= s1; v2 *= s0; v3 *= s1;
                }
                *(float2*)(C + (long)row * ldc + col)       = make_float2(v0, v1);
                *(float2*)(C + (long)(row + 8) * ldc + col) = make_float2(v2, v3);
            } else {
                __nv_bfloat16* C = (__nv_bfloat16*)Cv;
                const float b0 = bias[col], b1 = bias[col + 1];
                const float s0 = scalev[col], s1 = scalev[col + 1];
                const int f = col >> 1;
                {
                    float u = (acc[mf][nf][0] + b0) * s0;
                    float g = (acc[mf][nf][1] + b1) * s1;
                    C[(long)row * ldc + f] = __float2bfloat16(u * g / (1.0f + __expf(-g)));
                }
                {
                    float u = (acc[mf][nf][2] + b0) * s0;
                    float g = (acc[mf][nf][3] + b1) * s1;
                    C[(long)(row + 8) * ldc + f] = __float2bfloat16(u * g / (1.0f + __expf(-g)));
                }
            }
        }
    }
}

// ================= fused flash attention (bf16 output, KV reg-prefetch) =================
__global__ void __launch_bounds__(256)
flash_attn_k(const float* __restrict__ qkv, __nv_bfloat16* __restrict__ attnb)
{
    __shared__ uint32_t Qs[128 * 36];
    __shared__ uint32_t Ks[64 * 36];
    __shared__ uint32_t Vs[64 * 36];

    const int qb = blockIdx.x;
    const int hh = blockIdx.y;
    const int gg = hh >> 2;
    const int qcol = hh * HDIM;
    const int kcol = DM + gg * HDIM;
    const int vcol = DM + GHD + gg * HDIM;

    const int tid  = threadIdx.x;
    const int wid  = tid >> 5;
    const int lane = tid & 31;
    const int g4   = lane >> 2;
    const int t4   = lane & 3;
    const int wm   = wid * 16;
    const int s0q  = qb * 128;

    // Q tile -> smem (stores ordered by first sync inside loop)
    {
        int r = tid >> 1, half = tid & 1;
        const float* src = qkv + (long)(s0q + r) * QKV + qcol + half * 32;
        uint32_t* dst = Qs + r * 36 + half * 16;
#pragma unroll
        for (int i = 0; i < 8; i++) {
            float4 v = *(const float4*)(src + i * 4);
            dst[2 * i]     = packbf(v.x, v.y);
            dst[2 * i + 1] = packbf(v.z, v.w);
        }
    }

    // KV prefetch registers
    const int kr = tid >> 2, kq = tid & 3;       // K: 4 thr/row, 16 floats
    const int vd = tid & 63, vs = tid >> 6;      // V: 8 (pair) loads
    float4 kreg[4];
    float2 vreg[8];

    auto ldgKV = [&](int jb) {
        const int s0 = jb * 64;
        const float* ks = qkv + (long)(s0 + kr) * QKV + kcol + kq * 16;
#pragma unroll
        for (int i = 0; i < 4; i++) kreg[i] = *(const float4*)(ks + i * 4);
#pragma unroll
        for (int i = 0; i < 8; i++) {
            int sp = vs * 8 + i;
            const float* p0 = qkv + (long)(s0 + 2 * sp) * QKV + vcol + vd;
            vreg[i] = make_float2(p0[0], p0[QKV]);
        }
    };
    auto stsKV = [&]() {
        uint32_t* kd = Ks + kr * 36 + kq * 8;
#pragma unroll
        for (int i = 0; i < 4; i++) {
            kd[2 * i]     = packbf(kreg[i].x, kreg[i].y);
            kd[2 * i + 1] = packbf(kreg[i].z, kreg[i].w);
        }
#pragma unroll
        for (int i = 0; i < 8; i++)
            Vs[vd * 36 + vs * 8 + i] = packbf(vreg[i].x, vreg[i].y);
    };

    float O[8][4];
#pragma unroll
    for (int j = 0; j < 8; j++)
#pragma unroll
        for (int l = 0; l < 4; l++) O[j][l] = 0.0f;
    float m0 = -1e30f, m1 = -1e30f, l0 = 0.0f, l1 = 0.0f;

    const int nblk = 2 * qb + 2;
    ldgKV(0);

    for (int jb = 0; jb < nblk; jb++) {
        const int s0 = jb * 64;
        stsKV();
        __syncthreads();                         // KV (and Qs on jb=0) visible
        if (jb + 1 < nblk) ldgKV(jb + 1);        // overlapped with compute

        float S[8][4];
#pragma unroll
        for (int j = 0; j < 8; j++)
#pragma unroll
            for (int l = 0; l < 4; l++) S[j][l] = 0.0f;

#pragma unroll
        for (int kc = 0; kc < 4; kc++) {
            uint32_t a0 = Qs[(wm + g4    ) * 36 + kc * 8 + t4    ];
            uint32_t a1 = Qs[(wm + g4 + 8) * 36 + kc * 8 + t4    ];
            uint32_t a2 = Qs[(wm + g4    ) * 36 + kc * 8 + t4 + 4];
            uint32_t a3 = Qs[(wm + g4 + 8) * 36 + kc * 8 + t4 + 4];
#pragma unroll
            for (int nf = 0; nf < 8; nf++) {
                uint32_t b0 = Ks[(nf * 8 + g4) * 36 + kc * 8 + t4    ];
                uint32_t b1 = Ks[(nf * 8 + g4) * 36 + kc * 8 + t4 + 4];
                mma_bf16(S[nf], a0, a1, a2, a3, b0, b1);
            }
        }

        if (jb >= 2 * qb) {
            const int r0 = s0q + wm + g4, r1 = r0 + 8;
#pragma unroll
            for (int nf = 0; nf < 8; nf++) {
                const int c = s0 + nf * 8 + t4 * 2;
                if (c     > r0) S[nf][0] = -1e30f;
                if (c + 1 > r0) S[nf][1] = -1e30f;
                if (c     > r1) S[nf][2] = -1e30f;
                if (c + 1 > r1) S[nf][3] = -1e30f;
            }
        }

        float bm0 = -1e30f, bm1 = -1e30f;
#pragma unroll
        for (int nf = 0; nf < 8; nf++) {
            bm0 = fmaxf(bm0, fmaxf(S[nf][0], S[nf][1]));
            bm1 = fmaxf(bm1, fmaxf(S[nf][2], S[nf][3]));
        }
        bm0 = fmaxf(bm0, __shfl_xor_sync(0xffffffffu, bm0, 1));
        bm0 = fmaxf(bm0, __shfl_xor_sync(0xffffffffu, bm0, 2));
        bm1 = fmaxf(bm1, __shfl_xor_sync(0xffffffffu, bm1, 1));
        bm1 = fmaxf(bm1, __shfl_xor_sync(0xffffffffu, bm1, 2));

        float nm0 = fmaxf(m0, bm0), nm1 = fmaxf(m1, bm1);
        float sc0 = __expf(m0 - nm0), sc1 = __expf(m1 - nm1);
        m0 = nm0; m1 = nm1;

        float ps0 = 0.0f, ps1 = 0.0f;
#pragma unroll
        for (int nf = 0; nf < 8; nf++) {
            S[nf][0] = __expf(S[nf][0] - m0);
            S[nf][1] = __expf(S[nf][1] - m0);
            S[nf][2] = __expf(S[nf][2] - m1);
            S[nf][3] = __expf(S[nf][3] - m1);
            ps0 += S[nf][0] + S[nf][1];
            ps1 += S[nf][2] + S[nf][3];
        }
        ps0 += __shfl_xor_sync(0xffffffffu, ps0, 1);
        ps0 += __shfl_xor_sync(0xffffffffu, ps0, 2);
        ps1 += __shfl_xor_sync(0xffffffffu, ps1, 1);
        ps1 += __shfl_xor_sync(0xffffffffu, ps1, 2);
        l0 = l0 * sc0 + ps0;
        l1 = l1 * sc1 + ps1;

#pragma unroll
        for (int nf = 0; nf < 8; nf++) {
            O[nf][0] *= sc0; O[nf][1] *= sc0;
            O[nf][2] *= sc1; O[nf][3] *= sc1;
        }

#pragma unroll
        for (int kc = 0; kc < 4; kc++) {
            uint32_t ah0 = packbf(S[2*kc  ][0], S[2*kc  ][1]);
            uint32_t ah1 = packbf(S[2*kc  ][2], S[2*kc  ][3]);
            uint32_t ah2 = packbf(S[2*kc+1][0], S[2*kc+1][1]);
            uint32_t ah3 = packbf(S[2*kc+1][2], S[2*kc+1][3]);
            uint32_t al0 = packbf_res(S[2*kc  ][0], S[2*kc  ][1], ah0);
            uint32_t al1 = packbf_res(S[2*kc  ][2], S[2*kc  ][3], ah1);
            uint32_t al2 = packbf_res(S[2*kc+1][0], S[2*kc+1][1], ah2);
            uint32_t al3 = packbf_res(S[2*kc+1][2], S[2*kc+1][3], ah3);
#pragma unroll
            for (int nf = 0; nf < 8; nf++) {
                uint32_t b0 = Vs[(nf * 8 + g4) * 36 + kc * 8 + t4    ];
                uint32_t b1 = Vs[(nf * 8 + g4) * 36 + kc * 8 + t4 + 4];
                mma_bf16(O[nf], ah0, ah1, ah2, ah3, b0, b1);
                mma_bf16(O[nf], al0, al1, al2, al3, b0, b1);
            }
        }
        __syncthreads();                         // compute done before next stsKV
    }

    const float inv0 = 1.0f / l0, inv1 = 1.0f / l1;
    const int row0 = s0q + wm + g4;
#pragma unroll
    for (int nf = 0; nf < 8; nf++) {
        const int col = hh * HDIM + nf * 8 + t4 * 2;
        *(uint32_t*)(attnb + (long)row0 * DM + col) =
            packbf(O[nf][0] * inv0, O[nf][1] * inv0);
        *(uint32_t*)(attnb + (long)(row0 + 8) * DM + col) =
            packbf(O[nf][2] * inv1, O[nf][3] * inv1);
    }
}

// ---------------- embedding gather (fp32 + bf16 copies) ----------------
__global__ void embed_k(const int* __restrict__ x, const float* __restrict__ emb,
                        float* __restrict__ h, __nv_bfloat16* __restrict__ hb)
{
    int s = blockIdx.x;
    int t = threadIdx.x;
    float4 v = ((const float4*)(emb + (long)x[s] * DM))[t];
    ((float4*)(h + (long)s * DM))[t] = v;
    uint32_t* d = (uint32_t*)(hb + (long)s * DM) + t * 2;
    d[0] = packbf(v.x, v.y);
    d[1] = packbf(v.z, v.w);
}

// ---------------- merged RoPE + cosine-norm (Q and K), 8 units/block ----------------
__global__ void rope_norm_k(float* __restrict__ qkv, const float* __restrict__ sqk)
{
    const int u = blockIdx.x * 8 + (threadIdx.x >> 5);
    const int j = threadIdx.x & 31;
    const int s = u / (NH + NG);
    const int z = u - s * (NH + NG);
    float* base = qkv + (long)s * QKV + ((z < NH) ? z * HDIM : DM + (z - NH) * HDIM);
    float x1 = base[j], x2 = base[j + 32];

    float inv = powf(10000.0f, -(float)j / 32.0f);
    float ang = (float)s * inv;
    float sn, cs; sincosf(ang, &sn, &cs);
    float o1 = x1 * cs - x2 * sn;
    float o2 = x2 * cs + x1 * sn;

    float ss = o1 * o1 + o2 * o2;
#pragma unroll
    for (int off = 16; off > 0; off >>= 1)
        ss += __shfl_xor_sync(0xffffffffu, ss, off);
    float n = fmaxf(sqrtf(ss), 1e-6f);

    if (z < NH) {
        float e1 = sqk[z * HDIM + j]      * RTD;
        float e2 = sqk[z * HDIM + j + 32] * RTD;
        base[j]      = (o1 / n) * e1 * e1 * RTD;
        base[j + 32] = (o2 / n) * e2 * e2 * RTD;
    } else {
        base[j]      = o1 / n;
        base[j + 32] = o2 / n;
    }
}

// ---------------- residual lerp + cosine norm (writes fp32 + bf16) ----------------
__global__ void resid_norm_k(float* __restrict__ h, __nv_bfloat16* __restrict__ hb,
                             const float* __restrict__ t, const float* __restrict__ eig)
{
    int row = blockIdx.x;
    int tid = threadIdx.x;
    __shared__ float red[256];

    float4 tv = ((const float4*)(t + (long)row * DM))[tid];
    float ss = tv.x * tv.x + tv.y * tv.y + tv.z * tv.z + tv.w * tv.w;
    red[tid] = ss; __syncthreads();
    for (int o = 128; o > 0; o >>= 1) { if (tid < o) red[tid] += red[tid + o]; __syncthreads(); }
    float nt = fmaxf(sqrtf(red[0]), 1e-6f);
    __syncthreads();

    float4 hv = ((const float4*)(h + (long)row * DM))[tid];
    float4 ev = ((const float4*)eig)[tid];
    float4 r;
    r.x = hv.x + ev.x * RTDM * (tv.x / nt - hv.x);
    r.y = hv.y + ev.y * RTDM * (tv.y / nt - hv.y);
    r.z = hv.z + ev.z * RTDM * (tv.z / nt - hv.z);
    r.w = hv.w + ev.w * RTDM * (tv.w / nt - hv.w);

    float ss2 = r.x * r.x + r.y * r.y + r.z * r.z + r.w * r.w;
    red[tid] = ss2; __syncthreads();
    for (int o = 128; o > 0; o >>= 1) { if (tid < o) red[tid] += red[tid + o]; __syncthreads(); }
    float nr = fmaxf(sqrtf(red[0]), 1e-6f);

    r.x /= nr; r.y /= nr; r.z /= nr; r.w /= nr;
    ((float4*)(h + (long)row * DM))[tid] = r;
    uint32_t* d = (uint32_t*)(hb + (long)row * DM) + tid * 2;
    d[0] = packbf(r.x, r.y);
    d[1] = packbf(r.z, r.w);
}

// ---------------- final row softmax (online: 3 memory passes) ----------------
__global__ void softmax_full_k(float* __restrict__ out)
{
    int row = blockIdx.x;
    float* p = out + (long)row * NV;
    int t = threadIdx.x;
    __shared__ float rm[256], rs[256];

    float m = -1e30f, s = 0.0f;
    for (int j = t; j < NV; j += 256) {
        float v = p[j];
        if (v > m) { s = s * __expf(m - v) + 1.0f; m = v; }
        else       { s += __expf(v - m); }
    }
    rm[t] = m; rs[t] = s; __syncthreads();
    for (int o = 128; o > 0; o >>= 1) {
        if (t < o) {
            float m2 = rm[t + o], s2 = rs[t + o];
            float M = fmaxf(rm[t], m2);
            rs[t] = rs[t] * __expf(rm[t] - M) + s2 * __expf(m2 - M);
            rm[t] = M;
        }
        __syncthreads();
    }
    float M = rm[0];
    float inv = 1.0f / rs[0];
    for (int j = t; j < NV; j += 256) p[j] = __expf(p[j] - M) * inv;
}

// ---------------- host-side launchers ----------------
static void gemm128(const __nv_bfloat16* A, const __nv_bfloat16* B, float* C,
                    int M, int N, int K, int lda, int ldb, int ldc,
                    float alpha, const float* bias, const float* scalev, float beta)
{
    dim3 grid(N / 128, M / 128);
    bf16_gemm_k<128, 128, 0><<<grid, 256>>>(A, B, C, K, lda, ldb, ldc, alpha, bias, scalev, beta);
}
static void gemm_qkv(const __nv_bfloat16* A, const __nv_bfloat16* B, float* C,
                     int M, int N, int K, int lda, int ldb, int ldc,
                     float alpha, const float* bias)
{
    dim3 grid(N / 128, M / 64);
    bf16_gemm_k<64, 128, 0><<<grid, 256>>>(A, B, C, K, lda, ldb, ldc, alpha, bias, nullptr, 0.0f);
}
static void gemm_sm(const __nv_bfloat16* A, const __nv_bfloat16* B, float* C,
                    int M, int N, int K, int lda, int ldb, int ldc,
                    float alpha, const float* bias)
{
    dim3 grid(N / 64, M / 64);
    bf16_gemm_k<64, 64, 0><<<grid, 256>>>(A, B, C, K, lda, ldb, ldc, alpha, bias, nullptr, 0.0f);
}
static void gemm_swiglu(const __nv_bfloat16* A, const __nv_bfloat16* B, __nv_bfloat16* C,
                        int M, int N, int K, int lda, int ldb, int ldc,
                        const float* bias, const float* scalev)
{
    dim3 grid(N / 128, M / 128);
    bf16_gemm_k<128, 128, 1><<<grid, 256>>>(A, B, C, K, lda, ldb, ldc, 1.0f, bias, scalev, 1.0f);
}

extern "C" void kernel_launch(void* const* d_in, const int* in_sizes, int n_in,
                              void* d_out, int out_size)
{
    const int*   x      = (const int*)  d_in[0];
    const float* emb    = (const float*)d_in[1];
    const float* qw     = (const float*)d_in[2];
    const float* qb     = (const float*)d_in[3];
    const float* kw     = (const float*)d_in[4];
    const float* kb     = (const float*)d_in[5];
    const float* vw     = (const float*)d_in[6];
    const float* vb     = (const float*)d_in[7];
    const float* sqk    = (const float*)d_in[8];
    const float* ow     = (const float*)d_in[9];
    const float* ob     = (const float*)d_in[10];
    const float* w_in   = (const float*)d_in[11];
    const float* b_in   = (const float*)d_in[12];
    const float* w_gate = (const float*)d_in[13];
    const float* b_gate = (const float*)d_in[14];
    const float* w_out  = (const float*)d_in[15];
    const float* b_out  = (const float*)d_in[16];
    const float* s_u    = (const float*)d_in[17];
    const float* s_v    = (const float*)d_in[18];
    const float* eig_a  = (const float*)d_in[19];
    const float* eig_m  = (const float*)d_in[20];
    const float* out_w  = (const float*)d_in[21];
    const float* out_b  = (const float*)d_in[22];
    const float* s_z    = (const float*)d_in[23];
    float* out = (float*)d_out;

    float *h, *qkv, *t, *qkvb, *biog, *siog;
    __nv_bfloat16 *hb, *attnb, *ub, *qkvw, *wiog, *wout, *owb, *outwb;
    cudaGetSymbolAddress((void**)&h,     g_h);
    cudaGetSymbolAddress((void**)&qkv,   g_qkv);
    cudaGetSymbolAddress((void**)&t,     g_t);
    cudaGetSymbolAddress((void**)&qkvb,  g_qkvb);
    cudaGetSymbolAddress((void**)&biog,  g_biog);
    cudaGetSymbolAddress((void**)&siog,  g_siog);
    cudaGetSymbolAddress((void**)&hb,    g_hb);
    cudaGetSymbolAddress((void**)&attnb, g_attnb);
    cudaGetSymbolAddress((void**)&ub,    g_ub);
    cudaGetSymbolAddress((void**)&qkvw,  g_qkvw);
    cudaGetSymbolAddress((void**)&wiog,  g_wiog);
    cudaGetSymbolAddress((void**)&wout,  g_wout);
    cudaGetSymbolAddress((void**)&owb,   g_ow);
    cudaGetSymbolAddress((void**)&outwb, g_outw);

    cvt_all_k<<<CVT_GRID, 256>>>(qw, kw, vw, w_in, w_gate, w_out, ow, out_w,
                                 qb, kb, vb, b_in, b_gate, s_u, s_v);

    embed_k<<<SQ, 256>>>(x, emb, h, hb);

    for (int i = 0; i < NL; i++) {
        gemm_qkv(hb, qkvw + (long)i * QKV * DM, qkv, SQ, QKV, DM, DM, DM, QKV,
                 1.0f, qkvb + i * QKV);

        rope_norm_k<<<SQ * (NH + NG) / 8, 256>>>(qkv, sqk + (long)i * NH * HDIM);

        flash_attn_k<<<dim3(SQ / 128, NH), 256>>>(qkv, attnb);

        gemm_sm(attnb, owb + (long)i * DM * DM, t, SQ, DM, DM, DM, DM, DM,
                1.0f, ob + (long)i * DM);
        resid_norm_k<<<SQ, 256>>>(h, hb, t, eig_a + (long)i * DM);

        gemm_swiglu(hb, wiog + (long)i * 2 * DFF * DM, ub, SQ, 2 * DFF, DM, DM, DM, DFF,
                    biog + (long)i * 2 * DFF, siog + (long)i * 2 * DFF);
        gemm_sm(ub, wout + (long)i * DM * DFF, t, SQ, DM, DFF, DFF, DFF, DM,
                1.0f, b_out + (long)i * DM);
        resid_norm_k<<<SQ, 256>>>(h, hb, t, eig_m + (long)i * DM);
    }

    gemm128(hb, outwb, out, SQ, NV, DM, DM, DM, NV,
            1.0f, out_b, s_z, RTDM);
    softmax_full_k<<<SQ, 256>>>(out);
}

// round 13
// speedup vs baseline: 1.0031x; 1.0031x over previous
#include <cuda_runtime.h>
#include <cuda_bf16.h>
#include <math.h>
#include <stdint.h>

// ---------------- problem dims (fixed) ----------------
#define SQ   1024
#define DM   1024
#define NH   16
#define NG   4
#define HDIM 64
#define HPG  4
#define GHD  256
#define NL   4
#define DFF  4096
#define NV   32000
#define QKV  1536      // DM + 2*GHD
#define RTD  8.0f
#define RTDM 32.0f

// ---------------- device scratch ----------------
__device__ float g_h   [SQ * DM];
__device__ float g_qkv [SQ * QKV];
__device__ float g_t   [SQ * DM];
__device__ float g_qkvb[NL * QKV];
__device__ float g_biog[NL * 2 * DFF];
__device__ float g_siog[NL * 2 * DFF];

__device__ __align__(16) __nv_bfloat16 g_hb   [SQ * DM];
__device__ __align__(16) __nv_bfloat16 g_attnb[SQ * DM];
__device__ __align__(16) __nv_bfloat16 g_ub   [SQ * DFF];
__device__ __align__(16) __nv_bfloat16 g_qkvw [(long)NL * QKV * DM];
__device__ __align__(16) __nv_bfloat16 g_wiog [(long)NL * 2 * DFF * DM];
__device__ __align__(16) __nv_bfloat16 g_wout [(long)NL * DM * DFF];
__device__ __align__(16) __nv_bfloat16 g_ow   [(long)NL * DM * DM];
__device__ __align__(16) __nv_bfloat16 g_outw [(long)NV * DM];

__device__ __forceinline__ uint32_t packbf(float x, float y) {
    __nv_bfloat162 t = __floats2bfloat162_rn(x, y);
    return *reinterpret_cast<uint32_t*>(&t);
}
__device__ __forceinline__ uint32_t packbf_res(float x, float y, uint32_t hi) {
    __nv_bfloat162 h = *reinterpret_cast<__nv_bfloat162*>(&hi);
    return packbf(x - __bfloat162float(h.x), y - __bfloat162float(h.y));
}

__device__ __forceinline__ void mma_bf16(float c[4], uint32_t a0, uint32_t a1,
                                         uint32_t a2, uint32_t a3,
                                         uint32_t b0, uint32_t b1) {
    asm volatile(
        "mma.sync.aligned.m16n8k16.row.col.f32.bf16.bf16.f32 "
        "{%0,%1,%2,%3}, {%4,%5,%6,%7}, {%8,%9}, {%0,%1,%2,%3};"
        : "+f"(c[0]), "+f"(c[1]), "+f"(c[2]), "+f"(c[3])
        : "r"(a0), "r"(a1), "r"(a2), "r"(a3), "r"(b0), "r"(b1));
}

__device__ __forceinline__ void ldsm4(uint32_t r[4], uint32_t addr) {
    asm volatile(
        "ldmatrix.sync.aligned.m8n8.x4.shared.b16 {%0,%1,%2,%3}, [%4];"
        : "=r"(r[0]), "=r"(r[1]), "=r"(r[2]), "=r"(r[3]) : "r"(addr));
}

// ================= mega weight-conversion kernel (single launch, MLP=12) =================
#define E_QKVW  1572864L
#define E_WIOG  8388608L
#define E_WOUT  4194304L
#define E_OW    1048576L
#define E_OUTW  8192000L
#define CB0 (E_QKVW)
#define CB1 (CB0 + E_WIOG)
#define CB2 (CB1 + E_WOUT)
#define CB3 (CB2 + E_OW)
#define CB4 (CB3 + E_OUTW)
#define CB5 (CB4 + 1536L)
#define CB6 (CB5 + 16384L)
#define CVT_GRID 8192
#define CVT_STRIDE ((long)CVT_GRID * 256)

__global__ void cvt_all_k(const float* __restrict__ qw, const float* __restrict__ kw,
                          const float* __restrict__ vw, const float* __restrict__ w_in,
                          const float* __restrict__ w_gate, const float* __restrict__ w_out,
                          const float* __restrict__ ow, const float* __restrict__ out_w,
                          const float* __restrict__ qb, const float* __restrict__ kb,
                          const float* __restrict__ vb, const float* __restrict__ b_in,
                          const float* __restrict__ b_gate, const float* __restrict__ s_u,
                          const float* __restrict__ s_v)
{
    const long base = (long)blockIdx.x * 256 + threadIdx.x;
#pragma unroll
    for (int it = 0; it < 12; it++) {
        const long e = base + (long)it * CVT_STRIDE;
        if (e >= CB6) break;
        if (e < CB0) {
            long t = e;
            int l = (int)(t / 393216L);
            int rem = (int)(t - (long)l * 393216L);
            int row = rem >> 8, c4 = rem & 255;
            const float* src;
            if (row < DM)            src = qw + ((long)l * DM  + row)            * DM + c4 * 4;
            else if (row < DM + GHD) src = kw + ((long)l * GHD + row - DM)       * DM + c4 * 4;
            else                     src = vw + ((long)l * GHD + row - DM - GHD) * DM + c4 * 4;
            float4 v = *(const float4*)src;
            ((uint2*)g_qkvw)[t] = make_uint2(packbf(v.x, v.y), packbf(v.z, v.w));
        } else if (e < CB1) {
            long t = e - CB0;
            int l = (int)(t >> 21);
            int rem = (int)(t & 2097151L);
            int r = rem >> 8, c4 = rem & 255;
            const float* src = ((r & 1) ? w_gate : w_in)
                             + ((long)l * DFF + (r >> 1)) * DM + c4 * 4;
            float4 v = *(const float4*)src;
            ((uint2*)g_wiog)[t] = make_uint2(packbf(v.x, v.y), packbf(v.z, v.w));
        } else if (e < CB2) {
            long t = e - CB1;
            float4 v = ((const float4*)w_out)[t];
            ((uint2*)g_wout)[t] = make_uint2(packbf(v.x, v.y), packbf(v.z, v.w));
        } else if (e < CB3) {
            long t = e - CB2;
            float4 v = ((const float4*)ow)[t];
            ((uint2*)g_ow)[t] = make_uint2(packbf(v.x, v.y), packbf(v.z, v.w));
        } else if (e < CB4) {
            long t = e - CB3;
            float4 v = ((const float4*)out_w)[t];
            ((uint2*)g_outw)[t] = make_uint2(packbf(v.x, v.y), packbf(v.z, v.w));
        } else if (e < CB5) {
            int t = (int)(e - CB4);
            int l = t / 384, f4 = (t % 384) * 4;
            float4 v;
            if (f4 < DM)            v = *(const float4*)(qb + (long)l * DM  + f4);
            else if (f4 < DM + GHD) v = *(const float4*)(kb + (long)l * GHD + f4 - DM);
            else                    v = *(const float4*)(vb + (long)l * GHD + f4 - DM - GHD);
            *(float4*)(g_qkvb + (long)l * QKV + f4) = v;
        } else {
            int t = (int)(e - CB5);
            int l = t >> 12, f = t & (DFF - 1);
            g_biog[(long)l * 2 * DFF + 2 * f]     = b_in  [(long)l * DFF + f];
            g_biog[(long)l * 2 * DFF + 2 * f + 1] = b_gate[(long)l * DFF + f];
            g_siog[(long)l * 2 * DFF + 2 * f]     = s_u   [(long)l * DFF + f];
            g_siog[(long)l * 2 * DFF + 2 * f + 1] = s_v   [(long)l * DFF + f] * RTDM;
        }
    }
}

// ================= pure-bf16 TB GEMM, ldmatrix, single-sync mainloop =================
#define TASTR 20

template<int BMT, int BN, int EPI>
__global__ void __launch_bounds__(256, 2)
bf16_gemm_k(const __nv_bfloat16* __restrict__ A, const __nv_bfloat16* __restrict__ B,
            void* __restrict__ Cv, int K, int lda, int ldb, int ldc,
            float alpha, const float* __restrict__ bias,
            const float* __restrict__ scalev, float beta)
{
    constexpr int NF  = (BMT == 128) ? (BN / 16) : (BN / 32);
    constexpr int TAW = BMT * TASTR;
    constexpr int TBW = BN * TASTR;
    __shared__ __align__(16) uint32_t As[2 * TAW];
    __shared__ __align__(16) uint32_t Bs[2 * TBW];

    const int bm = blockIdx.y * BMT;
    const int bn = blockIdx.x * BN;
    const int tid  = threadIdx.x;
    const int wid  = tid >> 5;
    const int lane = tid & 31;
    const int g4   = lane >> 2;
    const int t4   = lane & 3;
    const int wm   = (BMT == 128) ? (wid & 3) * 32 : (wid & 1) * 32;
    const int wn   = (BMT == 128) ? (wid >> 2) * 64 : (wid >> 1) * (BN / 4);

    const uint32_t asb = (uint32_t)__cvta_generic_to_shared(As);
    const uint32_t bsb = (uint32_t)__cvta_generic_to_shared(Bs);
    const uint32_t aFrag = asb + 4u * ((wm + (lane & 15)) * TASTR + (lane >> 4) * 4);
    const uint32_t bFrag = bsb + 4u * ((wn + (lane & 15)) * TASTR + (lane >> 4) * 4);

    const int ra_ = (BMT == 128) ? (tid >> 1) : (tid >> 2);
    const int qa_ = (BMT == 128) ? (tid & 1)  : (tid & 3);
    const int rb_ = (BN  == 128) ? (tid >> 1) : (tid >> 2);
    const int hb_ = (BN  == 128) ? (tid & 1)  : (tid & 3);

    uint4 ra[2], rb[2];

    auto ldg = [&](int k0) {
        if (BMT == 128) {
            const __nv_bfloat16* pa = A + (long)(bm + ra_) * lda + k0 + qa_ * 16;
            ra[0] = *(const uint4*)pa; ra[1] = *(const uint4*)(pa + 8);
        } else {
            const __nv_bfloat16* pa = A + (long)(bm + ra_) * lda + k0 + qa_ * 8;
            ra[0] = *(const uint4*)pa;
        }
        if (BN == 128) {
            const __nv_bfloat16* pb = B + (long)(bn + rb_) * ldb + k0 + hb_ * 16;
            rb[0] = *(const uint4*)pb; rb[1] = *(const uint4*)(pb + 8);
        } else {
            const __nv_bfloat16* pb = B + (long)(bn + rb_) * ldb + k0 + hb_ * 8;
            rb[0] = *(const uint4*)pb;
        }
    };
    auto sts = [&](int buf) {
        if (BMT == 128) {
            uint32_t* da = As + buf * TAW + ra_ * TASTR + qa_ * 8;
            *(uint4*)da = ra[0]; *(uint4*)(da + 4) = ra[1];
        } else {
            uint32_t* da = As + buf * TAW + ra_ * TASTR + qa_ * 4;
            *(uint4*)da = ra[0];
        }
        if (BN == 128) {
            uint32_t* db = Bs + buf * TBW + rb_ * TASTR + hb_ * 8;
            *(uint4*)db = rb[0]; *(uint4*)(db + 4) = rb[1];
        } else {
            uint32_t* db = Bs + buf * TBW + rb_ * TASTR + hb_ * 4;
            *(uint4*)db = rb[0];
        }
    };

    float acc[2][NF][4];
#pragma unroll
    for (int i = 0; i < 2; i++)
#pragma unroll
        for (int j = 0; j < NF; j++)
#pragma unroll
            for (int l = 0; l < 4; l++) acc[i][j][l] = 0.0f;

    ldg(0);
    sts(0);
    __syncthreads();

    const int nsteps = K / 32;
    for (int ks = 0; ks < nsteps; ks++) {
        const bool more = (ks + 1 < nsteps);
        if (more) ldg((ks + 1) * 32);

        const uint32_t aB = aFrag + (ks & 1) * TAW * 4;
        const uint32_t bB = bFrag + (ks & 1) * TBW * 4;

#pragma unroll
        for (int kh = 0; kh < 2; kh++) {
            uint32_t af[2][4];
            ldsm4(af[0], aB + 4u * (kh * 8));
            ldsm4(af[1], aB + 4u * (16 * TASTR + kh * 8));
#pragma unroll
            for (int bf = 0; bf < NF / 2; bf++) {
                uint32_t bb[4];
                ldsm4(bb, bB + 4u * (bf * 16 * TASTR + kh * 8));
                mma_bf16(acc[0][2*bf  ], af[0][0], af[0][1], af[0][2], af[0][3], bb[0], bb[2]);
                mma_bf16(acc[1][2*bf  ], af[1][0], af[1][1], af[1][2], af[1][3], bb[0], bb[2]);
                mma_bf16(acc[0][2*bf+1], af[0][0], af[0][1], af[0][2], af[0][3], bb[1], bb[3]);
                mma_bf16(acc[1][2*bf+1], af[1][0], af[1][1], af[1][2], af[1][3], bb[1], bb[3]);
            }
        }

        if (more) sts((ks + 1) & 1);
        __syncthreads();
    }

#pragma unroll
    for (int mf = 0; mf < 2; mf++) {
#pragma unroll
        for (int nf = 0; nf < NF; nf++) {
            const int row = bm + wm + mf * 16 + g4;
            const int col = bn + wn + nf * 8 + t4 * 2;
            if (EPI == 0) {
                float* C = (float*)Cv;
                float v0 = acc[mf][nf][0] * alpha;
                float v1 = acc[mf][nf][1] * alpha;
                float v2 = acc[mf][nf][2] * alpha;
                float v3 = acc[mf][nf][3] * alpha;
                if (bias) {
                    float b0 = bias[col], b1 = bias[col + 1];
                    v0 += b0; v1 += b1; v2 += b0; v3 += b1;
                }
                if (scalev) {
                    float s0 = scalev[col] * beta, s1 = scalev[col + 1] * beta;
                    v0 *= s0; v1 *= s1; v2 *= s0; v3 *= s1;
                }
                *(float2*)(C + (long)row * ldc + col)       = make_float2(v0, v1);
                *(float2*)(C + (long)(row + 8) * ldc + col) = make_float2(v2, v3);
            } else {
                __nv_bfloat16* C = (__nv_bfloat16*)Cv;
                const float b0 = bias[col], b1 = bias[col + 1];
                const float s0 = scalev[col], s1 = scalev[col + 1];
                const int f = col >> 1;
                {
                    float u = (acc[mf][nf][0] + b0) * s0;
                    float g = (acc[mf][nf][1] + b1) * s1;
                    C[(long)row * ldc + f] = __float2bfloat16(u * g / (1.0f + __expf(-g)));
                }
                {
                    float u = (acc[mf][nf][2] + b0) * s0;
                    float g = (acc[mf][nf][3] + b1) * s1;
                    C[(long)(row + 8) * ldc + f] = __float2bfloat16(u * g / (1.0f + __expf(-g)));
                }
            }
        }
    }
}

// ================= fused flash attention (bf16 output) — proven R10 version =================
__global__ void __launch_bounds__(256)
flash_attn_k(const float* __restrict__ qkv, __nv_bfloat16* __restrict__ attnb)
{
    __shared__ uint32_t Qs[128 * 36];
    __shared__ uint32_t Ks[64 * 36];
    __shared__ uint32_t Vs[64 * 36];

    const int qb = blockIdx.x;
    const int hh = blockIdx.y;
    const int gg = hh >> 2;
    const int qcol = hh * HDIM;
    const int kcol = DM + gg * HDIM;
    const int vcol = DM + GHD + gg * HDIM;

    const int tid  = threadIdx.x;
    const int wid  = tid >> 5;
    const int lane = tid & 31;
    const int g4   = lane >> 2;
    const int t4   = lane & 3;
    const int wm   = wid * 16;
    const int s0q  = qb * 128;

    {
        int r = tid >> 1, half = tid & 1;
        const float* src = qkv + (long)(s0q + r) * QKV + qcol + half * 32;
        uint32_t* dst = Qs + r * 36 + half * 16;
#pragma unroll
        for (int i = 0; i < 8; i++) {
            float4 v = *(const float4*)(src + i * 4);
            dst[2 * i]     = packbf(v.x, v.y);
            dst[2 * i + 1] = packbf(v.z, v.w);
        }
    }

    float O[8][4];
#pragma unroll
    for (int j = 0; j < 8; j++)
#pragma unroll
        for (int l = 0; l < 4; l++) O[j][l] = 0.0f;
    float m0 = -1e30f, m1 = -1e30f, l0 = 0.0f, l1 = 0.0f;

    const int nblk = 2 * qb + 2;
    for (int jb = 0; jb < nblk; jb++) {
        const int s0 = jb * 64;
        __syncthreads();

        {
            int r = tid >> 2, q4 = tid & 3;
            const float* src = qkv + (long)(s0 + r) * QKV + kcol + q4 * 16;
            uint32_t* dst = Ks + r * 36 + q4 * 8;
#pragma unroll
            for (int i = 0; i < 4; i++) {
                float4 v = *(const float4*)(src + i * 4);
                dst[2 * i]     = packbf(v.x, v.y);
                dst[2 * i + 1] = packbf(v.z, v.w);
            }
        }
        {
            int d = tid & 63, sb = tid >> 6;
#pragma unroll
            for (int i = 0; i < 8; i++) {
                int sp = sb * 8 + i;
                const float* p0 = qkv + (long)(s0 + 2 * sp) * QKV + vcol + d;
                Vs[d * 36 + sp] = packbf(p0[0], p0[QKV]);
            }
        }
        __syncthreads();

        float S[8][4];
#pragma unroll
        for (int j = 0; j < 8; j++)
#pragma unroll
            for (int l = 0; l < 4; l++) S[j][l] = 0.0f;

#pragma unroll
        for (int kc = 0; kc < 4; kc++) {
            uint32_t a0 = Qs[(wm + g4    ) * 36 + kc * 8 + t4    ];
            uint32_t a1 = Qs[(wm + g4 + 8) * 36 + kc * 8 + t4    ];
            uint32_t a2 = Qs[(wm + g4    ) * 36 + kc * 8 + t4 + 4];
            uint32_t a3 = Qs[(wm + g4 + 8) * 36 + kc * 8 + t4 + 4];
#pragma unroll
            for (int nf = 0; nf < 8; nf++) {
                uint32_t b0 = Ks[(nf * 8 + g4) * 36 + kc * 8 + t4    ];
                uint32_t b1 = Ks[(nf * 8 + g4) * 36 + kc * 8 + t4 + 4];
                mma_bf16(S[nf], a0, a1, a2, a3, b0, b1);
            }
        }

        if (jb >= 2 * qb) {
            const int r0 = s0q + wm + g4, r1 = r0 + 8;
#pragma unroll
            for (int nf = 0; nf < 8; nf++) {
                const int c = s0 + nf * 8 + t4 * 2;
                if (c     > r0) S[nf][0] = -1e30f;
                if (c + 1 > r0) S[nf][1] = -1e30f;
                if (c     > r1) S[nf][2] = -1e30f;
                if (c + 1 > r1) S[nf][3] = -1e30f;
            }
        }

        float bm0 = -1e30f, bm1 = -1e30f;
#pragma unroll
        for (int nf = 0; nf < 8; nf++) {
            bm0 = fmaxf(bm0, fmaxf(S[nf][0], S[nf][1]));
            bm1 = fmaxf(bm1, fmaxf(S[nf][2], S[nf][3]));
        }
        bm0 = fmaxf(bm0, __shfl_xor_sync(0xffffffffu, bm0, 1));
        bm0 = fmaxf(bm0, __shfl_xor_sync(0xffffffffu, bm0, 2));
        bm1 = fmaxf(bm1, __shfl_xor_sync(0xffffffffu, bm1, 1));
        bm1 = fmaxf(bm1, __shfl_xor_sync(0xffffffffu, bm1, 2));

        float nm0 = fmaxf(m0, bm0), nm1 = fmaxf(m1, bm1);
        float sc0 = __expf(m0 - nm0), sc1 = __expf(m1 - nm1);
        m0 = nm0; m1 = nm1;

        float ps0 = 0.0f, ps1 = 0.0f;
#pragma unroll
        for (int nf = 0; nf < 8; nf++) {
            S[nf][0] = __expf(S[nf][0] - m0);
            S[nf][1] = __expf(S[nf][1] - m0);
            S[nf][2] = __expf(S[nf][2] - m1);
            S[nf][3] = __expf(S[nf][3] - m1);
            ps0 += S[nf][0] + S[nf][1];
            ps1 += S[nf][2] + S[nf][3];
        }
        ps0 += __shfl_xor_sync(0xffffffffu, ps0, 1);
        ps0 += __shfl_xor_sync(0xffffffffu, ps0, 2);
        ps1 += __shfl_xor_sync(0xffffffffu, ps1, 1);
        ps1 += __shfl_xor_sync(0xffffffffu, ps1, 2);
        l0 = l0 * sc0 + ps0;
        l1 = l1 * sc1 + ps1;

#pragma unroll
        for (int nf = 0; nf < 8; nf++) {
            O[nf][0] *= sc0; O[nf][1] *= sc0;
            O[nf][2] *= sc1; O[nf][3] *= sc1;
        }

#pragma unroll
        for (int kc = 0; kc < 4; kc++) {
            uint32_t ah0 = packbf(S[2*kc  ][0], S[2*kc  ][1]);
            uint32_t ah1 = packbf(S[2*kc  ][2], S[2*kc  ][3]);
            uint32_t ah2 = packbf(S[2*kc+1][0], S[2*kc+1][1]);
            uint32_t ah3 = packbf(S[2*kc+1][2], S[2*kc+1][3]);
            uint32_t al0 = packbf_res(S[2*kc  ][0], S[2*kc  ][1], ah0);
            uint32_t al1 = packbf_res(S[2*kc  ][2], S[2*kc  ][3], ah1);
            uint32_t al2 = packbf_res(S[2*kc+1][0], S[2*kc+1][1], ah2);
            uint32_t al3 = packbf_res(S[2*kc+1][2], S[2*kc+1][3], ah3);
#pragma unroll
            for (int nf = 0; nf < 8; nf++) {
                uint32_t b0 = Vs[(nf * 8 + g4) * 36 + kc * 8 + t4    ];
                uint32_t b1 = Vs[(nf * 8 + g4) * 36 + kc * 8 + t4 + 4];
                mma_bf16(O[nf], ah0, ah1, ah2, ah3, b0, b1);
                mma_bf16(O[nf], al0, al1, al2, al3, b0, b1);
            }
        }
    }

    const float inv0 = 1.0f / l0, inv1 = 1.0f / l1;
    const int row0 = s0q + wm + g4;
#pragma unroll
    for (int nf = 0; nf < 8; nf++) {
        const int col = hh * HDIM + nf * 8 + t4 * 2;
        *(uint32_t*)(attnb + (long)row0 * DM + col) =
            packbf(O[nf][0] * inv0, O[nf][1] * inv0);
        *(uint32_t*)(attnb + (long)(row0 + 8) * DM + col) =
            packbf(O[nf][2] * inv1, O[nf][3] * inv1);
    }
}

// ---------------- embedding gather (fp32 + bf16 copies) ----------------
__global__ void embed_k(const int* __restrict__ x, const float* __restrict__ emb,
                        float* __restrict__ h, __nv_bfloat16* __restrict__ hb)
{
    int s = blockIdx.x;
    int t = threadIdx.x;
    float4 v = ((const float4*)(emb + (long)x[s] * DM))[t];
    ((float4*)(h + (long)s * DM))[t] = v;
    uint32_t* d = (uint32_t*)(hb + (long)s * DM) + t * 2;
    d[0] = packbf(v.x, v.y);
    d[1] = packbf(v.z, v.w);
}

// ---------------- merged RoPE + cosine-norm (Q and K), 8 units/block ----------------
__global__ void rope_norm_k(float* __restrict__ qkv, const float* __restrict__ sqk)
{
    const int u = blockIdx.x * 8 + (threadIdx.x >> 5);
    const int j = threadIdx.x & 31;
    const int s = u / (NH + NG);
    const int z = u - s * (NH + NG);
    float* base = qkv + (long)s * QKV + ((z < NH) ? z * HDIM : DM + (z - NH) * HDIM);
    float x1 = base[j], x2 = base[j + 32];

    float inv = powf(10000.0f, -(float)j / 32.0f);
    float ang = (float)s * inv;
    float sn, cs; sincosf(ang, &sn, &cs);
    float o1 = x1 * cs - x2 * sn;
    float o2 = x2 * cs + x1 * sn;

    float ss = o1 * o1 + o2 * o2;
#pragma unroll
    for (int off = 16; off > 0; off >>= 1)
        ss += __shfl_xor_sync(0xffffffffu, ss, off);
    float n = fmaxf(sqrtf(ss), 1e-6f);

    if (z < NH) {
        float e1 = sqk[z * HDIM + j]      * RTD;
        float e2 = sqk[z * HDIM + j + 32] * RTD;
        base[j]      = (o1 / n) * e1 * e1 * RTD;
        base[j + 32] = (o2 / n) * e2 * e2 * RTD;
    } else {
        base[j]      = o1 / n;
        base[j + 32] = o2 / n;
    }
}

// ---------------- residual lerp + cosine norm (writes fp32 + bf16) ----------------
__global__ void resid_norm_k(float* __restrict__ h, __nv_bfloat16* __restrict__ hb,
                             const float* __restrict__ t, const float* __restrict__ eig)
{
    int row = blockIdx.x;
    int tid = threadIdx.x;
    __shared__ float red[256];

    float4 tv = ((const float4*)(t + (long)row * DM))[tid];
    float ss = tv.x * tv.x + tv.y * tv.y + tv.z * tv.z + tv.w * tv.w;
    red[tid] = ss; __syncthreads();
    for (int o = 128; o > 0; o >>= 1) { if (tid < o) red[tid] += red[tid + o]; __syncthreads(); }
    float nt = fmaxf(sqrtf(red[0]), 1e-6f);
    __syncthreads();

    float4 hv = ((const float4*)(h + (long)row * DM))[tid];
    float4 ev = ((const float4*)eig)[tid];
    float4 r;
    r.x = hv.x + ev.x * RTDM * (tv.x / nt - hv.x);
    r.y = hv.y + ev.y * RTDM * (tv.y / nt - hv.y);
    r.z = hv.z + ev.z * RTDM * (tv.z / nt - hv.z);
    r.w = hv.w + ev.w * RTDM * (tv.w / nt - hv.w);

    float ss2 = r.x * r.x + r.y * r.y + r.z * r.z + r.w * r.w;
    red[tid] = ss2; __syncthreads();
    for (int o = 128; o > 0; o >>= 1) { if (tid < o) red[tid] += red[tid + o]; __syncthreads(); }
    float nr = fmaxf(sqrtf(red[0]), 1e-6f);

    r.x /= nr; r.y /= nr; r.z /= nr; r.w /= nr;
    ((float4*)(h + (long)row * DM))[tid] = r;
    uint32_t* d = (uint32_t*)(hb + (long)row * DM) + tid * 2;
    d[0] = packbf(r.x, r.y);
    d[1] = packbf(r.z, r.w);
}

// ---------------- final row softmax (online: 3 memory passes) ----------------
__global__ void softmax_full_k(float* __restrict__ out)
{
    int row = blockIdx.x;
    float* p = out + (long)row * NV;
    int t = threadIdx.x;
    __shared__ float rm[256], rs[256];

    float m = -1e30f, s = 0.0f;
    for (int j = t; j < NV; j += 256) {
        float v = p[j];
        if (v > m) { s = s * __expf(m - v) + 1.0f; m = v; }
        else       { s += __expf(v - m); }
    }
    rm[t] = m; rs[t] = s; __syncthreads();
    for (int o = 128; o > 0; o >>= 1) {
        if (t < o) {
            float m2 = rm[t + o], s2 = rs[t + o];
            float M = fmaxf(rm[t], m2);
            rs[t] = rs[t] * __expf(rm[t] - M) + s2 * __expf(m2 - M);
            rm[t] = M;
        }
        __syncthreads();
    }
    float M = rm[0];
    float inv = 1.0f / rs[0];
    for (int j = t; j < NV; j += 256) p[j] = __expf(p[j] - M) * inv;
}

// ---------------- host-side launchers ----------------
static void gemm128(const __nv_bfloat16* A, const __nv_bfloat16* B, float* C,
                    int M, int N, int K, int lda, int ldb, int ldc,
                    float alpha, const float* bias, const float* scalev, float beta)
{
    dim3 grid(N / 128, M / 128);
    bf16_gemm_k<128, 128, 0><<<grid, 256>>>(A, B, C, K, lda, ldb, ldc, alpha, bias, scalev, beta);
}
static void gemm_qkv(const __nv_bfloat16* A, const __nv_bfloat16* B, float* C,
                     int M, int N, int K, int lda, int ldb, int ldc,
                     float alpha, const float* bias)
{
    dim3 grid(N / 128, M / 64);
    bf16_gemm_k<64, 128, 0><<<grid, 256>>>(A, B, C, K, lda, ldb, ldc, alpha, bias, nullptr, 0.0f);
}
static void gemm_sm(const __nv_bfloat16* A, const __nv_bfloat16* B, float* C,
                    int M, int N, int K, int lda, int ldb, int ldc,
                    float alpha, const float* bias)
{
    dim3 grid(N / 64, M / 64);
    bf16_gemm_k<64, 64, 0><<<grid, 256>>>(A, B, C, K, lda, ldb, ldc, alpha, bias, nullptr, 0.0f);
}
static void gemm_swiglu(const __nv_bfloat16* A, const __nv_bfloat16* B, __nv_bfloat16* C,
                        int M, int N, int K, int lda, int ldb, int ldc,
                        const float* bias, const float* scalev)
{
    dim3 grid(N / 128, M / 128);
    bf16_gemm_k<128, 128, 1><<<grid, 256>>>(A, B, C, K, lda, ldb, ldc, 1.0f, bias, scalev, 1.0f);
}

extern "C" void kernel_launch(void* const* d_in, const int* in_sizes, int n_in,
                              void* d_out, int out_size)
{
    const int*   x      = (const int*)  d_in[0];
    const float* emb    = (const float*)d_in[1];
    const float* qw     = (const float*)d_in[2];
    const float* qb     = (const float*)d_in[3];
    const float* kw     = (const float*)d_in[4];
    const float* kb     = (const float*)d_in[5];
    const float* vw     = (const float*)d_in[6];
    const float* vb     = (const float*)d_in[7];
    const float* sqk    = (const float*)d_in[8];
    const float* ow     = (const float*)d_in[9];
    const float* ob     = (const float*)d_in[10];
    const float* w_in   = (const float*)d_in[11];
    const float* b_in   = (const float*)d_in[12];
    const float* w_gate = (const float*)d_in[13];
    const float* b_gate = (const float*)d_in[14];
    const float* w_out  = (const float*)d_in[15];
    const float* b_out  = (const float*)d_in[16];
    const float* s_u    = (const float*)d_in[17];
    const float* s_v    = (const float*)d_in[18];
    const float* eig_a  = (const float*)d_in[19];
    const float* eig_m  = (const float*)d_in[20];
    const float* out_w  = (const float*)d_in[21];
    const float* out_b  = (const float*)d_in[22];
    const float* s_z    = (const float*)d_in[23];
    float* out = (float*)d_out;

    float *h, *qkv, *t, *qkvb, *biog, *siog;
    __nv_bfloat16 *hb, *attnb, *ub, *qkvw, *wiog, *wout, *owb, *outwb;
    cudaGetSymbolAddress((void**)&h,     g_h);
    cudaGetSymbolAddress((void**)&qkv,   g_qkv);
    cudaGetSymbolAddress((void**)&t,     g_t);
    cudaGetSymbolAddress((void**)&qkvb,  g_qkvb);
    cudaGetSymbolAddress((void**)&biog,  g_biog);
    cudaGetSymbolAddress((void**)&siog,  g_siog);
    cudaGetSymbolAddress((void**)&hb,    g_hb);
    cudaGetSymbolAddress((void**)&attnb, g_attnb);
    cudaGetSymbolAddress((void**)&ub,    g_ub);
    cudaGetSymbolAddress((void**)&qkvw,  g_qkvw);
    cudaGetSymbolAddress((void**)&wiog,  g_wiog);
    cudaGetSymbolAddress((void**)&wout,  g_wout);
    cudaGetSymbolAddress((void**)&owb,   g_ow);
    cudaGetSymbolAddress((void**)&outwb, g_outw);

    cvt_all_k<<<CVT_GRID, 256>>>(qw, kw, vw, w_in, w_gate, w_out, ow, out_w,
                                 qb, kb, vb, b_in, b_gate, s_u, s_v);

    embed_k<<<SQ, 256>>>(x, emb, h, hb);

    for (int i = 0; i < NL; i++) {
        gemm_qkv(hb, qkvw + (long)i * QKV * DM, qkv, SQ, QKV, DM, DM, DM, QKV,
                 1.0f, qkvb + i * QKV);

        rope_norm_k<<<SQ * (NH + NG) / 8, 256>>>(qkv, sqk + (long)i * NH * HDIM);

        flash_attn_k<<<dim3(SQ / 128, NH), 256>>>(qkv, attnb);

        gemm_sm(attnb, owb + (long)i * DM * DM, t, SQ, DM, DM, DM, DM, DM,
                1.0f, ob + (long)i * DM);
        resid_norm_k<<<SQ, 256>>>(h, hb, t, eig_a + (long)i * DM);

        gemm_swiglu(hb, wiog + (long)i * 2 * DFF * DM, ub, SQ, 2 * DFF, DM, DM, DM, DFF,
                    biog + (long)i * 2 * DFF, siog + (long)i * 2 * DFF);
        gemm_sm(ub, wout + (long)i * DM * DFF, t, SQ, DM, DFF, DFF, DFF, DM,
                1.0f, b_out + (long)i * DM);
        resid_norm_k<<<SQ, 256>>>(h, hb, t, eig_m + (long)i * DM);
    }

    gemm128(hb, outwb, out, SQ, NV, DM, DM, DM, NV,
            1.0f, out_b, s_z, RTDM);
    softmax_full_k<<<SQ, 256>>>(out);
}

// round 15
// speedup vs baseline: 1.0086x; 1.0055x over previous
#include <cuda_runtime.h>
#include <cuda_bf16.h>
#include <math.h>
#include <stdint.h>

// ---------------- problem dims (fixed) ----------------
#define SQ   1024
#define DM   1024
#define NH   16
#define NG   4
#define HDIM 64
#define HPG  4
#define GHD  256
#define NL   4
#define DFF  4096
#define NV   32000
#define QKV  1536      // DM + 2*GHD
#define RTD  8.0f
#define RTDM 32.0f

// ---------------- device scratch ----------------
__device__ float g_h   [SQ * DM];
__device__ float g_qkv [SQ * QKV];
__device__ float g_t   [SQ * DM];
__device__ float g_qkvb[NL * QKV];
__device__ float g_biog[NL * 2 * DFF];
__device__ float g_siog[NL * 2 * DFF];

__device__ __align__(16) __nv_bfloat16 g_hb   [SQ * DM];
__device__ __align__(16) __nv_bfloat16 g_attnb[SQ * DM];
__device__ __align__(16) __nv_bfloat16 g_ub   [SQ * DFF];
__device__ __align__(16) __nv_bfloat16 g_qkvw [(long)NL * QKV * DM];
__device__ __align__(16) __nv_bfloat16 g_wiog [(long)NL * 2 * DFF * DM];
__device__ __align__(16) __nv_bfloat16 g_wout [(long)NL * DM * DFF];
__device__ __align__(16) __nv_bfloat16 g_ow   [(long)NL * DM * DM];
__device__ __align__(16) __nv_bfloat16 g_outw [(long)NV * DM];

__device__ __forceinline__ uint32_t packbf(float x, float y) {
    __nv_bfloat162 t = __floats2bfloat162_rn(x, y);
    return *reinterpret_cast<uint32_t*>(&t);
}
__device__ __forceinline__ uint32_t packbf_res(float x, float y, uint32_t hi) {
    __nv_bfloat162 h = *reinterpret_cast<__nv_bfloat162*>(&hi);
    return packbf(x - __bfloat162float(h.x), y - __bfloat162float(h.y));
}

__device__ __forceinline__ void mma_bf16(float c[4], uint32_t a0, uint32_t a1,
                                         uint32_t a2, uint32_t a3,
                                         uint32_t b0, uint32_t b1) {
    asm volatile(
        "mma.sync.aligned.m16n8k16.row.col.f32.bf16.bf16.f32 "
        "{%0,%1,%2,%3}, {%4,%5,%6,%7}, {%8,%9}, {%0,%1,%2,%3};"
        : "+f"(c[0]), "+f"(c[1]), "+f"(c[2]), "+f"(c[3])
        : "r"(a0), "r"(a1), "r"(a2), "r"(a3), "r"(b0), "r"(b1));
}

__device__ __forceinline__ void ldsm4(uint32_t r[4], uint32_t addr) {
    asm volatile(
        "ldmatrix.sync.aligned.m8n8.x4.shared.b16 {%0,%1,%2,%3}, [%4];"
        : "=r"(r[0]), "=r"(r[1]), "=r"(r[2]), "=r"(r[3]) : "r"(addr));
}

// ================= mega weight-conversion kernel (single launch) =================
#define E_QKVW  1572864L
#define E_WIOG  8388608L
#define E_WOUT  4194304L
#define E_OW    1048576L
#define E_OUTW  8192000L
#define CB0 (E_QKVW)
#define CB1 (CB0 + E_WIOG)
#define CB2 (CB1 + E_WOUT)
#define CB3 (CB2 + E_OW)
#define CB4 (CB3 + E_OUTW)
#define CB5 (CB4 + 1536L)
#define CB6 (CB5 + 16384L)

__global__ void cvt_all_k(const float* __restrict__ qw, const float* __restrict__ kw,
                          const float* __restrict__ vw, const float* __restrict__ w_in,
                          const float* __restrict__ w_gate, const float* __restrict__ w_out,
                          const float* __restrict__ ow, const float* __restrict__ out_w,
                          const float* __restrict__ qb, const float* __restrict__ kb,
                          const float* __restrict__ vb, const float* __restrict__ b_in,
                          const float* __restrict__ b_gate, const float* __restrict__ s_u,
                          const float* __restrict__ s_v)
{
    for (long e = (long)blockIdx.x * 256 + threadIdx.x; e < CB6;
         e += (long)gridDim.x * 256) {
        if (e < CB0) {
            long t = e;
            int l = (int)(t / 393216L);
            int rem = (int)(t - (long)l * 393216L);
            int row = rem >> 8, c4 = rem & 255;
            const float* src;
            if (row < DM)            src = qw + ((long)l * DM  + row)            * DM + c4 * 4;
            else if (row < DM + GHD) src = kw + ((long)l * GHD + row - DM)       * DM + c4 * 4;
            else                     src = vw + ((long)l * GHD + row - DM - GHD) * DM + c4 * 4;
            float4 v = *(const float4*)src;
            ((uint2*)g_qkvw)[t] = make_uint2(packbf(v.x, v.y), packbf(v.z, v.w));
        } else if (e < CB1) {
            long t = e - CB0;
            int l = (int)(t >> 21);
            int rem = (int)(t & 2097151L);
            int r = rem >> 8, c4 = rem & 255;
            const float* src = ((r & 1) ? w_gate : w_in)
                             + ((long)l * DFF + (r >> 1)) * DM + c4 * 4;
            float4 v = *(const float4*)src;
            ((uint2*)g_wiog)[t] = make_uint2(packbf(v.x, v.y), packbf(v.z, v.w));
        } else if (e < CB2) {
            long t = e - CB1;
            float4 v = ((const float4*)w_out)[t];
            ((uint2*)g_wout)[t] = make_uint2(packbf(v.x, v.y), packbf(v.z, v.w));
        } else if (e < CB3) {
            long t = e - CB2;
            float4 v = ((const float4*)ow)[t];
            ((uint2*)g_ow)[t] = make_uint2(packbf(v.x, v.y), packbf(v.z, v.w));
        } else if (e < CB4) {
            long t = e - CB3;
            float4 v = ((const float4*)out_w)[t];
            ((uint2*)g_outw)[t] = make_uint2(packbf(v.x, v.y), packbf(v.z, v.w));
        } else if (e < CB5) {
            int t = (int)(e - CB4);
            int l = t / 384, f4 = (t % 384) * 4;
            float4 v;
            if (f4 < DM)            v = *(const float4*)(qb + (long)l * DM  + f4);
            else if (f4 < DM + GHD) v = *(const float4*)(kb + (long)l * GHD + f4 - DM);
            else                    v = *(const float4*)(vb + (long)l * GHD + f4 - DM - GHD);
            *(float4*)(g_qkvb + (long)l * QKV + f4) = v;
        } else {
            int t = (int)(e - CB5);
            int l = t >> 12, f = t & (DFF - 1);
            g_biog[(long)l * 2 * DFF + 2 * f]     = b_in  [(long)l * DFF + f];
            g_biog[(long)l * 2 * DFF + 2 * f + 1] = b_gate[(long)l * DFF + f];
            g_siog[(long)l * 2 * DFF + 2 * f]     = s_u   [(long)l * DFF + f];
            g_siog[(long)l * 2 * DFF + 2 * f + 1] = s_v   [(long)l * DFF + f] * RTDM;
        }
    }
}

// ================= pure-bf16 TB GEMM, ldmatrix, single-sync mainloop =================
// Tiles BMT x BN x 32, 256 threads. 64-row tiles get 3 CTAs/SM (reg cap 85),
// 128-row tiles keep the proven 2 CTAs/SM.
#define TASTR 20

template<int BMT, int BN, int EPI>
__global__ void __launch_bounds__(256, (BMT == 128) ? 2 : 3)
bf16_gemm_k(const __nv_bfloat16* __restrict__ A, const __nv_bfloat16* __restrict__ B,
            void* __restrict__ Cv, int K, int lda, int ldb, int ldc,
            float alpha, const float* __restrict__ bias,
            const float* __restrict__ scalev, float beta)
{
    constexpr int NF  = (BMT == 128) ? (BN / 16) : (BN / 32);
    constexpr int TAW = BMT * TASTR;
    constexpr int TBW = BN * TASTR;
    __shared__ __align__(16) uint32_t As[2 * TAW];
    __shared__ __align__(16) uint32_t Bs[2 * TBW];

    const int bm = blockIdx.y * BMT;
    const int bn = blockIdx.x * BN;
    const int tid  = threadIdx.x;
    const int wid  = tid >> 5;
    const int lane = tid & 31;
    const int g4   = lane >> 2;
    const int t4   = lane & 3;
    const int wm   = (BMT == 128) ? (wid & 3) * 32 : (wid & 1) * 32;
    const int wn   = (BMT == 128) ? (wid >> 2) * 64 : (wid >> 1) * (BN / 4);

    const uint32_t asb = (uint32_t)__cvta_generic_to_shared(As);
    const uint32_t bsb = (uint32_t)__cvta_generic_to_shared(Bs);
    const uint32_t aFrag = asb + 4u * ((wm + (lane & 15)) * TASTR + (lane >> 4) * 4);
    const uint32_t bFrag = bsb + 4u * ((wn + (lane & 15)) * TASTR + (lane >> 4) * 4);

    const int ra_ = (BMT == 128) ? (tid >> 1) : (tid >> 2);
    const int qa_ = (BMT == 128) ? (tid & 1)  : (tid & 3);
    const int rb_ = (BN  == 128) ? (tid >> 1) : (tid >> 2);
    const int hb_ = (BN  == 128) ? (tid & 1)  : (tid & 3);

    uint4 ra[2], rb[2];

    auto ldg = [&](int k0) {
        if (BMT == 128) {
            const __nv_bfloat16* pa = A + (long)(bm + ra_) * lda + k0 + qa_ * 16;
            ra[0] = *(const uint4*)pa; ra[1] = *(const uint4*)(pa + 8);
        } else {
            const __nv_bfloat16* pa = A + (long)(bm + ra_) * lda + k0 + qa_ * 8;
            ra[0] = *(const uint4*)pa;
        }
        if (BN == 128) {
            const __nv_bfloat16* pb = B + (long)(bn + rb_) * ldb + k0 + hb_ * 16;
            rb[0] = *(const uint4*)pb; rb[1] = *(const uint4*)(pb + 8);
        } else {
            const __nv_bfloat16* pb = B + (long)(bn + rb_) * ldb + k0 + hb_ * 8;
            rb[0] = *(const uint4*)pb;
        }
    };
    auto sts = [&](int buf) {
        if (BMT == 128) {
            uint32_t* da = As + buf * TAW + ra_ * TASTR + qa_ * 8;
            *(uint4*)da = ra[0]; *(uint4*)(da + 4) = ra[1];
        } else {
            uint32_t* da = As + buf * TAW + ra_ * TASTR + qa_ * 4;
            *(uint4*)da = ra[0];
        }
        if (BN == 128) {
            uint32_t* db = Bs + buf * TBW + rb_ * TASTR + hb_ * 8;
            *(uint4*)db = rb[0]; *(uint4*)(db + 4) = rb[1];
        } else {
            uint32_t* db = Bs + buf * TBW + rb_ * TASTR + hb_ * 4;
            *(uint4*)db = rb[0];
        }
    };

    float acc[2][NF][4];
#pragma unroll
    for (int i = 0; i < 2; i++)
#pragma unroll
        for (int j = 0; j < NF; j++)
#pragma unroll
            for (int l = 0; l < 4; l++) acc[i][j][l] = 0.0f;

    ldg(0);
    sts(0);
    __syncthreads();

    const int nsteps = K / 32;
    for (int ks = 0; ks < nsteps; ks++) {
        const bool more = (ks + 1 < nsteps);
        if (more) ldg((ks + 1) * 32);

        const uint32_t aB = aFrag + (ks & 1) * TAW * 4;
        const uint32_t bB = bFrag + (ks & 1) * TBW * 4;

#pragma unroll
        for (int kh = 0; kh < 2; kh++) {
            uint32_t af[2][4];
            ldsm4(af[0], aB + 4u * (kh * 8));
            ldsm4(af[1], aB + 4u * (16 * TASTR + kh * 8));
#pragma unroll
            for (int bf = 0; bf < NF / 2; bf++) {
                uint32_t bb[4];
                ldsm4(bb, bB + 4u * (bf * 16 * TASTR + kh * 8));
                mma_bf16(acc[0][2*bf  ], af[0][0], af[0][1], af[0][2], af[0][3], bb[0], bb[2]);
                mma_bf16(acc[1][2*bf  ], af[1][0], af[1][1], af[1][2], af[1][3], bb[0], bb[2]);
                mma_bf16(acc[0][2*bf+1], af[0][0], af[0][1], af[0][2], af[0][3], bb[1], bb[3]);
                mma_bf16(acc[1][2*bf+1], af[1][0], af[1][1], af[1][2], af[1][3], bb[1], bb[3]);
            }
        }

        if (more) sts((ks + 1) & 1);
        __syncthreads();
    }

#pragma unroll
    for (int mf = 0; mf < 2; mf++) {
#pragma unroll
        for (int nf = 0; nf < NF; nf++) {
            const int row = bm + wm + mf * 16 + g4;
            const int col = bn + wn + nf * 8 + t4 * 2;
            if (EPI == 0) {
                float* C = (float*)Cv;
                float v0 = acc[mf][nf][0] * alpha;
                float v1 = acc[mf][nf][1] * alpha;
                float v2 = acc[mf][nf][2] * alpha;
                float v3 = acc[mf][nf][3] * alpha;
                if (bias) {
                    float b0 = bias[col], b1 = bias[col + 1];
                    v0 += b0; v1 += b1; v2 += b0; v3 += b1;
                }
                if (scalev) {
                    float s0 = scalev[col] * beta, s1 = scalev[col + 1] * beta;
                    v0 *= s0; v1 *= s1; v2 *= s0; v3 *= s1;
                }
                *(float2*)(C + (long)row * ldc + col)       = make_float2(v0, v1);
                *(float2*)(C + (long)(row + 8) * ldc + col) = make_float2(v2, v3);
            } else {
                __nv_bfloat16* C = (__nv_bfloat16*)Cv;
                const float b0 = bias[col], b1 = bias[col + 1];
                const float s0 = scalev[col], s1 = scalev[col + 1];
                const int f = col >> 1;
                {
                    float u = (acc[mf][nf][0] + b0) * s0;
                    float g = (acc[mf][nf][1] + b1) * s1;
                    C[(long)row * ldc + f] = __float2bfloat16(u * g / (1.0f + __expf(-g)));
                }
                {
                    float u = (acc[mf][nf][2] + b0) * s0;
                    float g = (acc[mf][nf][3] + b1) * s1;
                    C[(long)(row + 8) * ldc + f] = __float2bfloat16(u * g / (1.0f + __expf(-g)));
                }
            }
        }
    }
}

// ================= fused flash attention (bf16 output) — proven R10 version =================
__global__ void __launch_bounds__(256)
flash_attn_k(const float* __restrict__ qkv, __nv_bfloat16* __restrict__ attnb)
{
    __shared__ uint32_t Qs[128 * 36];
    __shared__ uint32_t Ks[64 * 36];
    __shared__ uint32_t Vs[64 * 36];

    const int qb = blockIdx.x;
    const int hh = blockIdx.y;
    const int gg = hh >> 2;
    const int qcol = hh * HDIM;
    const int kcol = DM + gg * HDIM;
    const int vcol = DM + GHD + gg * HDIM;

    const int tid  = threadIdx.x;
    const int wid  = tid >> 5;
    const int lane = tid & 31;
    const int g4   = lane >> 2;
    const int t4   = lane & 3;
    const int wm   = wid * 16;
    const int s0q  = qb * 128;

    {
        int r = tid >> 1, half = tid & 1;
        const float* src = qkv + (long)(s0q + r) * QKV + qcol + half * 32;
        uint32_t* dst = Qs + r * 36 + half * 16;
#pragma unroll
        for (int i = 0; i < 8; i++) {
            float4 v = *(const float4*)(src + i * 4);
            dst[2 * i]     = packbf(v.x, v.y);
            dst[2 * i + 1] = packbf(v.z, v.w);
        }
    }

    float O[8][4];
#pragma unroll
    for (int j = 0; j < 8; j++)
#pragma unroll
        for (int l = 0; l < 4; l++) O[j][l] = 0.0f;
    float m0 = -1e30f, m1 = -1e30f, l0 = 0.0f, l1 = 0.0f;

    const int nblk = 2 * qb + 2;
    for (int jb = 0; jb < nblk; jb++) {
        const int s0 = jb * 64;
        __syncthreads();

        {
            int r = tid >> 2, q4 = tid & 3;
            const float* src = qkv + (long)(s0 + r) * QKV + kcol + q4 * 16;
            uint32_t* dst = Ks + r * 36 + q4 * 8;
#pragma unroll
            for (int i = 0; i < 4; i++) {
                float4 v = *(const float4*)(src + i * 4);
                dst[2 * i]     = packbf(v.x, v.y);
                dst[2 * i + 1] = packbf(v.z, v.w);
            }
        }
        {
            int d = tid & 63, sb = tid >> 6;
#pragma unroll
            for (int i = 0; i < 8; i++) {
                int sp = sb * 8 + i;
                const float* p0 = qkv + (long)(s0 + 2 * sp) * QKV + vcol + d;
                Vs[d * 36 + sp] = packbf(p0[0], p0[QKV]);
            }
        }
        __syncthreads();

        float S[8][4];
#pragma unroll
        for (int j = 0; j < 8; j++)
#pragma unroll
            for (int l = 0; l < 4; l++) S[j][l] = 0.0f;

#pragma unroll
        for (int kc = 0; kc < 4; kc++) {
            uint32_t a0 = Qs[(wm + g4    ) * 36 + kc * 8 + t4    ];
            uint32_t a1 = Qs[(wm + g4 + 8) * 36 + kc * 8 + t4    ];
            uint32_t a2 = Qs[(wm + g4    ) * 36 + kc * 8 + t4 + 4];
            uint32_t a3 = Qs[(wm + g4 + 8) * 36 + kc * 8 + t4 + 4];
#pragma unroll
            for (int nf = 0; nf < 8; nf++) {
                uint32_t b0 = Ks[(nf * 8 + g4) * 36 + kc * 8 + t4    ];
                uint32_t b1 = Ks[(nf * 8 + g4) * 36 + kc * 8 + t4 + 4];
                mma_bf16(S[nf], a0, a1, a2, a3, b0, b1);
            }
        }

        if (jb >= 2 * qb) {
            const int r0 = s0q + wm + g4, r1 = r0 + 8;
#pragma unroll
            for (int nf = 0; nf < 8; nf++) {
                const int c = s0 + nf * 8 + t4 * 2;
                if (c     > r0) S[nf][0] = -1e30f;
                if (c + 1 > r0) S[nf][1] = -1e30f;
                if (c     > r1) S[nf][2] = -1e30f;
                if (c + 1 > r1) S[nf][3] = -1e30f;
            }
        }

        float bm0 = -1e30f, bm1 = -1e30f;
#pragma unroll
        for (int nf = 0; nf < 8; nf++) {
            bm0 = fmaxf(bm0, fmaxf(S[nf][0], S[nf][1]));
            bm1 = fmaxf(bm1, fmaxf(S[nf][2], S[nf][3]));
        }
        bm0 = fmaxf(bm0, __shfl_xor_sync(0xffffffffu, bm0, 1));
        bm0 = fmaxf(bm0, __shfl_xor_sync(0xffffffffu, bm0, 2));
        bm1 = fmaxf(bm1, __shfl_xor_sync(0xffffffffu, bm1, 1));
        bm1 = fmaxf(bm1, __shfl_xor_sync(0xffffffffu, bm1, 2));

        float nm0 = fmaxf(m0, bm0), nm1 = fmaxf(m1, bm1);
        float sc0 = __expf(m0 - nm0), sc1 = __expf(m1 - nm1);
        m0 = nm0; m1 = nm1;

        float ps0 = 0.0f, ps1 = 0.0f;
#pragma unroll
        for (int nf = 0; nf < 8; nf++) {
            S[nf][0] = __expf(S[nf][0] - m0);
            S[nf][1] = __expf(S[nf][1] - m0);
            S[nf][2] = __expf(S[nf][2] - m1);
            S[nf][3] = __expf(S[nf][3] - m1);
            ps0 += S[nf][0] + S[nf][1];
            ps1 += S[nf][2] + S[nf][3];
        }
        ps0 += __shfl_xor_sync(0xffffffffu, ps0, 1);
        ps0 += __shfl_xor_sync(0xffffffffu, ps0, 2);
        ps1 += __shfl_xor_sync(0xffffffffu, ps1, 1);
        ps1 += __shfl_xor_sync(0xffffffffu, ps1, 2);
        l0 = l0 * sc0 + ps0;
        l1 = l1 * sc1 + ps1;

#pragma unroll
        for (int nf = 0; nf < 8; nf++) {
            O[nf][0] *= sc0; O[nf][1] *= sc0;
            O[nf][2] *= sc1; O[nf][3] *= sc1;
        }

#pragma unroll
        for (int kc = 0; kc < 4; kc++) {
            uint32_t ah0 = packbf(S[2*kc  ][0], S[2*kc  ][1]);
            uint32_t ah1 = packbf(S[2*kc  ][2], S[2*kc  ][3]);
            uint32_t ah2 = packbf(S[2*kc+1][0], S[2*kc+1][1]);
            uint32_t ah3 = packbf(S[2*kc+1][2], S[2*kc+1][3]);
            uint32_t al0 = packbf_res(S[2*kc  ][0], S[2*kc  ][1], ah0);
            uint32_t al1 = packbf_res(S[2*kc  ][2], S[2*kc  ][3], ah1);
            uint32_t al2 = packbf_res(S[2*kc+1][0], S[2*kc+1][1], ah2);
            uint32_t al3 = packbf_res(S[2*kc+1][2], S[2*kc+1][3], ah3);
#pragma unroll
            for (int nf = 0; nf < 8; nf++) {
                uint32_t b0 = Vs[(nf * 8 + g4) * 36 + kc * 8 + t4    ];
                uint32_t b1 = Vs[(nf * 8 + g4) * 36 + kc * 8 + t4 + 4];
                mma_bf16(O[nf], ah0, ah1, ah2, ah3, b0, b1);
                mma_bf16(O[nf], al0, al1, al2, al3, b0, b1);
            }
        }
    }

    const float inv0 = 1.0f / l0, inv1 = 1.0f / l1;
    const int row0 = s0q + wm + g4;
#pragma unroll
    for (int nf = 0; nf < 8; nf++) {
        const int col = hh * HDIM + nf * 8 + t4 * 2;
        *(uint32_t*)(attnb + (long)row0 * DM + col) =
            packbf(O[nf][0] * inv0, O[nf][1] * inv0);
        *(uint32_t*)(attnb + (long)(row0 + 8) * DM + col) =
            packbf(O[nf][2] * inv1, O[nf][3] * inv1);
    }
}

// ---------------- embedding gather (fp32 + bf16 copies) ----------------
__global__ void embed_k(const int* __restrict__ x, const float* __restrict__ emb,
                        float* __restrict__ h, __nv_bfloat16* __restrict__ hb)
{
    int s = blockIdx.x;
    int t = threadIdx.x;
    float4 v = ((const float4*)(emb + (long)x[s] * DM))[t];
    ((float4*)(h + (long)s * DM))[t] = v;
    uint32_t* d = (uint32_t*)(hb + (long)s * DM) + t * 2;
    d[0] = packbf(v.x, v.y);
    d[1] = packbf(v.z, v.w);
}

// ---------------- merged RoPE + cosine-norm (Q and K), 8 units/block ----------------
__global__ void rope_norm_k(float* __restrict__ qkv, const float* __restrict__ sqk)
{
    const int u = blockIdx.x * 8 + (threadIdx.x >> 5);
    const int j = threadIdx.x & 31;
    const int s = u / (NH + NG);
    const int z = u - s * (NH + NG);
    float* base = qkv + (long)s * QKV + ((z < NH) ? z * HDIM : DM + (z - NH) * HDIM);
    float x1 = base[j], x2 = base[j + 32];

    float inv = powf(10000.0f, -(float)j / 32.0f);
    float ang = (float)s * inv;
    float sn, cs; sincosf(ang, &sn, &cs);
    float o1 = x1 * cs - x2 * sn;
    float o2 = x2 * cs + x1 * sn;

    float ss = o1 * o1 + o2 * o2;
#pragma unroll
    for (int off = 16; off > 0; off >>= 1)
        ss += __shfl_xor_sync(0xffffffffu, ss, off);
    float n = fmaxf(sqrtf(ss), 1e-6f);

    if (z < NH) {
        float e1 = sqk[z * HDIM + j]      * RTD;
        float e2 = sqk[z * HDIM + j + 32] * RTD;
        base[j]      = (o1 / n) * e1 * e1 * RTD;
        base[j + 32] = (o2 / n) * e2 * e2 * RTD;
    } else {
        base[j]      = o1 / n;
        base[j + 32] = o2 / n;
    }
}

// ---------------- residual lerp + cosine norm (writes fp32 + bf16) ----------------
__global__ void resid_norm_k(float* __restrict__ h, __nv_bfloat16* __restrict__ hb,
                             const float* __restrict__ t, const float* __restrict__ eig)
{
    int row = blockIdx.x;
    int tid = threadIdx.x;
    __shared__ float red[256];

    float4 tv = ((const float4*)(t + (long)row * DM))[tid];
    float ss = tv.x * tv.x + tv.y * tv.y + tv.z * tv.z + tv.w * tv.w;
    red[tid] = ss; __syncthreads();
    for (int o = 128; o > 0; o >>= 1) { if (tid < o) red[tid] += red[tid + o]; __syncthreads(); }
    float nt = fmaxf(sqrtf(red[0]), 1e-6f);
    __syncthreads();

    float4 hv = ((const float4*)(h + (long)row * DM))[tid];
    float4 ev = ((const float4*)eig)[tid];
    float4 r;
    r.x = hv.x + ev.x * RTDM * (tv.x / nt - hv.x);
    r.y = hv.y + ev.y * RTDM * (tv.y / nt - hv.y);
    r.z = hv.z + ev.z * RTDM * (tv.z / nt - hv.z);
    r.w = hv.w + ev.w * RTDM * (tv.w / nt - hv.w);

    float ss2 = r.x * r.x + r.y * r.y + r.z * r.z + r.w * r.w;
    red[tid] = ss2; __syncthreads();
    for (int o = 128; o > 0; o >>= 1) { if (tid < o) red[tid] += red[tid + o]; __syncthreads(); }
    float nr = fmaxf(sqrtf(red[0]), 1e-6f);

    r.x /= nr; r.y /= nr; r.z /= nr; r.w /= nr;
    ((float4*)(h + (long)row * DM))[tid] = r;
    uint32_t* d = (uint32_t*)(hb + (long)row * DM) + tid * 2;
    d[0] = packbf(r.x, r.y);
    d[1] = packbf(r.z, r.w);
}

// ---------------- final row softmax (online: 3 memory passes) ----------------
__global__ void softmax_full_k(float* __restrict__ out)
{
    int row = blockIdx.x;
    float* p = out + (long)row * NV;
    int t = threadIdx.x;
    __shared__ float rm[256], rs[256];

    float m = -1e30f, s = 0.0f;
    for (int j = t; j < NV; j += 256) {
        float v = p[j];
        if (v > m) { s = s * __expf(m - v) + 1.0f; m = v; }
        else       { s += __expf(v - m); }
    }
    rm[t] = m; rs[t] = s; __syncthreads();
    for (int o = 128; o > 0; o >>= 1) {
        if (t < o) {
            float m2 = rm[t + o], s2 = rs[t + o];
            float M = fmaxf(rm[t], m2);
            rs[t] = rs[t] * __expf(rm[t] - M) + s2 * __expf(m2 - M);
            rm[t] = M;
        }
        __syncthreads();
    }
    float M = rm[0];
    float inv = 1.0f / rs[0];
    for (int j = t; j < NV; j += 256) p[j] = __expf(p[j] - M) * inv;
}

// ---------------- host-side launchers ----------------
static void gemm128(const __nv_bfloat16* A, const __nv_bfloat16* B, float* C,
                    int M, int N, int K, int lda, int ldb, int ldc,
                    float alpha, const float* bias, const float* scalev, float beta)
{
    dim3 grid(N / 128, M / 128);
    bf16_gemm_k<128, 128, 0><<<grid, 256>>>(A, B, C, K, lda, ldb, ldc, alpha, bias, scalev, beta);
}
static void gemm_qkv(const __nv_bfloat16* A, const __nv_bfloat16* B, float* C,
                     int M, int N, int K, int lda, int ldb, int ldc,
                     float alpha, const float* bias)
{
    dim3 grid(N / 128, M / 64);
    bf16_gemm_k<64, 128, 0><<<grid, 256>>>(A, B, C, K, lda, ldb, ldc, alpha, bias, nullptr, 0.0f);
}
static void gemm_sm(const __nv_bfloat16* A, const __nv_bfloat16* B, float* C,
                    int M, int N, int K, int lda, int ldb, int ldc,
                    float alpha, const float* bias)
{
    dim3 grid(N / 64, M / 64);
    bf16_gemm_k<64, 64, 0><<<grid, 256>>>(A, B, C, K, lda, ldb, ldc, alpha, bias, nullptr, 0.0f);
}
static void gemm_swiglu(const __nv_bfloat16* A, const __nv_bfloat16* B, __nv_bfloat16* C,
                        int M, int N, int K, int lda, int ldb, int ldc,
                        const float* bias, const float* scalev)
{
    dim3 grid(N / 128, M / 128);
    bf16_gemm_k<128, 128, 1><<<grid, 256>>>(A, B, C, K, lda, ldb, ldc, 1.0f, bias, scalev, 1.0f);
}

extern "C" void kernel_launch(void* const* d_in, const int* in_sizes, int n_in,
                              void* d_out, int out_size)
{
    const int*   x      = (const int*)  d_in[0];
    const float* emb    = (const float*)d_in[1];
    const float* qw     = (const float*)d_in[2];
    const float* qb     = (const float*)d_in[3];
    const float* kw     = (const float*)d_in[4];
    const float* kb     = (const float*)d_in[5];
    const float* vw     = (const float*)d_in[6];
    const float* vb     = (const float*)d_in[7];
    const float* sqk    = (const float*)d_in[8];
    const float* ow     = (const float*)d_in[9];
    const float* ob     = (const float*)d_in[10];
    const float* w_in   = (const float*)d_in[11];
    const float* b_in   = (const float*)d_in[12];
    const float* w_gate = (const float*)d_in[13];
    const float* b_gate = (const float*)d_in[14];
    const float* w_out  = (const float*)d_in[15];
    const float* b_out  = (const float*)d_in[16];
    const float* s_u    = (const float*)d_in[17];
    const float* s_v    = (const float*)d_in[18];
    const float* eig_a  = (const float*)d_in[19];
    const float* eig_m  = (const float*)d_in[20];
    const float* out_w  = (const float*)d_in[21];
    const float* out_b  = (const float*)d_in[22];
    const float* s_z    = (const float*)d_in[23];
    float* out = (float*)d_out;

    float *h, *qkv, *t, *qkvb, *biog, *siog;
    __nv_bfloat16 *hb, *attnb, *ub, *qkvw, *wiog, *wout, *owb, *outwb;
    cudaGetSymbolAddress((void**)&h,     g_h);
    cudaGetSymbolAddress((void**)&qkv,   g_qkv);
    cudaGetSymbolAddress((void**)&t,     g_t);
    cudaGetSymbolAddress((void**)&qkvb,  g_qkvb);
    cudaGetSymbolAddress((void**)&biog,  g_biog);
    cudaGetSymbolAddress((void**)&siog,  g_siog);
    cudaGetSymbolAddress((void**)&hb,    g_hb);
    cudaGetSymbolAddress((void**)&attnb, g_attnb);
    cudaGetSymbolAddress((void**)&ub,    g_ub);
    cudaGetSymbolAddress((void**)&qkvw,  g_qkvw);
    cudaGetSymbolAddress((void**)&wiog,  g_wiog);
    cudaGetSymbolAddress((void**)&wout,  g_wout);
    cudaGetSymbolAddress((void**)&owb,   g_ow);
    cudaGetSymbolAddress((void**)&outwb, g_outw);

    cvt_all_k<<<8192, 256>>>(qw, kw, vw, w_in, w_gate, w_out, ow, out_w,
                             qb, kb, vb, b_in, b_gate, s_u, s_v);

    embed_k<<<SQ, 256>>>(x, emb, h, hb);

    for (int i = 0; i < NL; i++) {
        gemm_qkv(hb, qkvw + (long)i * QKV * DM, qkv, SQ, QKV, DM, DM, DM, QKV,
                 1.0f, qkvb + i * QKV);

        rope_norm_k<<<SQ * (NH + NG) / 8, 256>>>(qkv, sqk + (long)i * NH * HDIM);

        flash_attn_k<<<dim3(SQ / 128, NH), 256>>>(qkv, attnb);

        gemm_sm(attnb, owb + (long)i * DM * DM, t, SQ, DM, DM, DM, DM, DM,
                1.0f, ob + (long)i * DM);
        resid_norm_k<<<SQ, 256>>>(h, hb, t, eig_a + (long)i * DM);

        gemm_swiglu(hb, wiog + (long)i * 2 * DFF * DM, ub, SQ, 2 * DFF, DM, DM, DM, DFF,
                    biog + (long)i * 2 * DFF, siog + (long)i * 2 * DFF);
        gemm_sm(ub, wout + (long)i * DM * DFF, t, SQ, DM, DFF, DFF, DFF, DM,
                1.0f, b_out + (long)i * DM);
        resid_norm_k<<<SQ, 256>>>(h, hb, t, eig_m + (long)i * DM);
    }

    gemm128(hb, outwb, out, SQ, NV, DM, DM, DM, NV,
            1.0f, out_b, s_z, RTDM);
    softmax_full_k<<<SQ, 256>>>(out);
}